// round 15
// baseline (speedup 1.0000x reference)
#include <cuda_runtime.h>
#include <cuda_fp16.h>
#include <math.h>
#include <stdint.h>

#define HB 4
#define CC 192
#define HW 65536
#define HW2 16384
#define HEADS 6
#define CHD 32

typedef unsigned short u16;

// ---------------- static scratch ----------------
__device__ float g_A[100663296];      // 402 MB
__device__ float g_B[100663296];      // 402 MB
__device__ u16   g_Xh[50331648];      // x fp16 plane
__device__ u16   g_Wh[393216];        // weights fp16
__device__ float g_part[32 * 24 * 1024];
__device__ float g_A0[24 * 1024];
__device__ float g_pq[24576];
__device__ float g_pk[24576];

#define WO_Q0    0
#define WO_KV0   49152
#define WO_Q1    122880
#define WO_KV1   172032
#define WO_P0    245760
#define WO_P1    294912
#define WO_DS    344064

// ================= helpers =================
__device__ __forceinline__ u16 h16(float v) {
    __half h = __float2half_rn(v);
    return *(u16*)&h;
}
__device__ __forceinline__ float hff(u16 s) {
    __half h = *(__half*)&s;
    return __half2float(h);
}
__device__ __forceinline__ uint32_t pack2(u16 a, u16 b) {
    return (uint32_t)a | ((uint32_t)b << 16);
}
__device__ __forceinline__ uint32_t smem_u32(const void* p) {
    uint32_t a;
    asm("{ .reg .u64 t; cvta.to.shared.u64 t, %1; cvt.u32.u64 %0, t; }" : "=r"(a) : "l"(p));
    return a;
}
__device__ __forceinline__ void mma16816(float* d, const uint32_t* a, const uint32_t* b) {
    asm volatile(
        "mma.sync.aligned.m16n8k16.row.col.f32.f16.f16.f32 "
        "{%0,%1,%2,%3}, {%4,%5,%6,%7}, {%8,%9}, {%0,%1,%2,%3};"
        : "+f"(d[0]), "+f"(d[1]), "+f"(d[2]), "+f"(d[3])
        : "r"(a[0]), "r"(a[1]), "r"(a[2]), "r"(a[3]), "r"(b[0]), "r"(b[1]));
}
__device__ __forceinline__ void ldsm4(uint32_t* r, uint32_t addr) {
    asm volatile("ldmatrix.sync.aligned.m8n8.x4.shared.b16 {%0,%1,%2,%3}, [%4];"
        : "=r"(r[0]), "=r"(r[1]), "=r"(r[2]), "=r"(r[3]) : "r"(addr));
}
__device__ __forceinline__ void ldsm4t(uint32_t* r, uint32_t addr) {
    asm volatile("ldmatrix.sync.aligned.m8n8.x4.trans.shared.b16 {%0,%1,%2,%3}, [%4];"
        : "=r"(r[0]), "=r"(r[1]), "=r"(r[2]), "=r"(r[3]) : "r"(addr));
}
__device__ __forceinline__ void cpa16(uint32_t dst, const void* src) {
    asm volatile("cp.async.cg.shared.global [%0], [%1], 16;" :: "r"(dst), "l"(src));
}
#define CP_COMMIT() asm volatile("cp.async.commit_group;" ::: "memory")
#define CP_WAIT0()  asm volatile("cp.async.wait_group 0;" ::: "memory")
#define CP_WAIT1()  asm volatile("cp.async.wait_group 1;" ::: "memory")

// fast exp on FMA pipe
__device__ __forceinline__ float fexp(float x) {
    float t = x * 1.44269504089f;
    t = fmaxf(t, -126.f);
    float fi = rintf(t);
    float f = t - fi;
    float p = 0.00015403530393f;
    p = fmaf(p, f, 0.00133335581464f);
    p = fmaf(p, f, 0.00961812910763f);
    p = fmaf(p, f, 0.05550410866482f);
    p = fmaf(p, f, 0.24022650695910f);
    p = fmaf(p, f, 0.69314718055995f);
    p = fmaf(p, f, 1.0f);
    int i = (int)fi;
    float s = __int_as_float((i + 127) << 23);
    return p * s;
}

// ---------------- conversion kernels ----------------
__global__ void cvtx_kernel(const float* __restrict__ src, u16* __restrict__ hi, int n4)
{
    int i = blockIdx.x * 256 + threadIdx.x;
    if (i >= n4) return;
    float4 v = *(const float4*)(src + (size_t)i * 4);
    ushort4 hh = {h16(v.x), h16(v.y), h16(v.z), h16(v.w)};
    *(ushort4*)(hi + (size_t)i * 4) = hh;
}

__global__ void cvtw_all_kernel(const float* __restrict__ Wq0, const float* __restrict__ Wkv0,
                                const float* __restrict__ Wq1, const float* __restrict__ Wkv1,
                                const float* __restrict__ Wp0, const float* __restrict__ Wp1,
                                const float* __restrict__ Wds,
                                u16* __restrict__ hi)
{
    int i = blockIdx.x * 256 + threadIdx.x;
    if (i >= 2048 * CC) return;
    int row = i / CC;
    const float* src; int r0, oc;
    if (row < 256)       { src = Wq0;  r0 = 0;    oc = 192; }
    else if (row < 640)  { src = Wkv0; r0 = 256;  oc = 384; }
    else if (row < 896)  { src = Wq1;  r0 = 640;  oc = 192; }
    else if (row < 1280) { src = Wkv1; r0 = 896;  oc = 384; }
    else if (row < 1536) { src = Wp0;  r0 = 1280; oc = 192; }
    else if (row < 1792) { src = Wp1;  r0 = 1536; oc = 192; }
    else                 { src = Wds;  r0 = 1792; oc = 192; }
    int lr = row - r0;
    float v = (lr < oc) ? src[(size_t)lr * CC + (i % CC)] : 0.f;
    hi[i] = h16(v);
}

// ---------------- pipelined fp16 GEMM with row-active tail skip ----------------
#define ASTR 40
#define BSTR 136
#define A_BUF_U (128 * ASTR)
#define B_BUF_U (32 * BSTR)
#define GEMM_SMEM ((2 * A_BUF_U + 2 * B_BUF_U) * 2)

__global__ void __launch_bounds__(256, 2)
mma_gemm2(const u16* __restrict__ Xs, const u16* __restrict__ Wm,
          const float* __restrict__ resid, float* __restrict__ Yf,
          u16* __restrict__ Yh,
          int OC, int P, int ycnt, int mode)
{
    extern __shared__ u16 smu[];
    const uint32_t sbA = smem_u32(smu);
    const uint32_t sbB = sbA + 2 * A_BUF_U * 2;

    const int tid = threadIdx.x;
    const int warp = tid >> 5, lane = tid & 31;
    const int g4 = lane >> 2, t4 = lane & 3;
    const int wm = warp >> 1, wn = warp & 1;
    const int gz = blockIdx.z;
    const int bx = blockIdx.x / ycnt;
    const int by = blockIdx.x - bx * ycnt;
    const int oc0 = by * 128;
    const int p0 = bx * 128;
    const size_t xoff = (size_t)gz * CC * P + p0;

    const bool act0 = (oc0 + wm * 32) < OC;
    const bool act1 = (oc0 + wm * 32 + 16) < OC;

    float acc[2][8][4];
#pragma unroll
    for (int mt = 0; mt < 2; mt++)
#pragma unroll
        for (int nt = 0; nt < 8; nt++)
#pragma unroll
            for (int e = 0; e < 4; e++) acc[mt][nt][e] = 0.f;

    auto prefetch = [&](int kc, int buf) {
        const int kbase = kc * 32;
        const uint32_t abase = sbA + buf * A_BUF_U * 2;
#pragma unroll
        for (int i = 0; i < 2; i++) {
            int op = tid + i * 256;
            int row = op >> 2, cq = op & 3;
            const u16* src = Wm + (size_t)(oc0 + row) * CC + kbase + cq * 8;
            uint32_t dst = abase + (uint32_t)(row * ASTR + cq * 8) * 2;
            cpa16(dst, src);
        }
        const uint32_t bbase = sbB + buf * B_BUF_U * 2;
#pragma unroll
        for (int i = 0; i < 2; i++) {
            int op = tid + i * 256;
            int row = op >> 4, cq = op & 15;
            const u16* src = Xs + xoff + (size_t)(kbase + row) * P + cq * 8;
            uint32_t dst = bbase + (uint32_t)(row * BSTR + cq * 8) * 2;
            cpa16(dst, src);
        }
    };

    prefetch(0, 0);
    CP_COMMIT();

    const int KC = CC / 32;
    for (int kc = 0; kc < KC; kc++) {
        if (kc + 1 < KC) {
            prefetch(kc + 1, (kc + 1) & 1);
            CP_COMMIT();
            CP_WAIT1();
        } else {
            CP_WAIT0();
        }
        __syncthreads();

        if (act0) {
            const int buf = kc & 1;
            const uint32_t aoff = sbA + buf * A_BUF_U * 2;
            const uint32_t boff = sbB + buf * B_BUF_U * 2;
#pragma unroll
            for (int ks = 0; ks < 2; ks++) {
                const int k0 = ks * 16;
                uint32_t ah[2][4];
                {
                    int mrow = wm * 32 + (lane & 15);
                    int kk = k0 + ((lane & 16) >> 1);
                    ldsm4(ah[0], aoff + (uint32_t)(mrow * ASTR + kk) * 2);
                    if (act1)
                        ldsm4(ah[1], aoff + (uint32_t)((mrow + 16) * ASTR + kk) * 2);
                }
#pragma unroll
                for (int np = 0; np < 4; np++) {
                    int krow = k0 + (lane & 15);
                    int ncol = wn * 64 + np * 16 + ((lane & 16) >> 1);
                    uint32_t bh[4];
                    ldsm4t(bh, boff + (uint32_t)(krow * BSTR + ncol) * 2);
#pragma unroll
                    for (int half = 0; half < 2; half++) {
                        int nt = np * 2 + half;
                        uint32_t* bhp = bh + half * 2;
                        mma16816(acc[0][nt], ah[0], bhp);
                        if (act1) mma16816(acc[1][nt], ah[1], bhp);
                    }
                }
            }
        }
        __syncthreads();
    }

#pragma unroll
    for (int mt = 0; mt < 2; mt++) {
        int r0 = oc0 + wm * 32 + mt * 16 + g4;
#pragma unroll
        for (int nt = 0; nt < 8; nt++) {
            int p = p0 + wn * 64 + nt * 8 + t4 * 2;
#pragma unroll
            for (int hrow = 0; hrow < 2; hrow++) {
                int r = r0 + hrow * 8;
                if (r >= OC) continue;
                float v0 = acc[mt][nt][hrow * 2 + 0];
                float v1 = acc[mt][nt][hrow * 2 + 1];
                if (mode == 3) {
                    int w = p >> 6, t = p & 63;
                    int yy = t >> 3, xx = t & 7;
                    int b = w >> 10;
                    int wh = (w >> 5) & 31;
                    int wn2 = w & 31;
                    int y = (wh * 8 + yy + 4) & 255;
                    int x = (wn2 * 8 + xx + 4) & 255;
                    size_t o = ((size_t)b * CC + r) * HW + y * 256 + x;
                    float2 prev = *(float2*)(Yf + o);
                    *(float2*)(Yf + o) = make_float2(prev.x + v0, prev.y + v1);
                } else {
                    size_t o;
                    if (mode == 2) {
                        int sy = p >> 8, sx = p & 255;
                        int wh = sy >> 3, yy = sy & 7;
                        int ww = sx >> 3, xx = sx & 7;
                        int k = wh >> 3;
                        int whp = ((wh & 7) << 1) | (ww >> 4);
                        int wwp = ww & 15;
                        int img = gz * 4 + k;
                        o = ((size_t)img * CC + r) * HW2 + (whp * 8 + yy) * 128 + wwp * 8 + xx;
                    } else {
                        o = ((size_t)gz * OC + r) * P + p;
                        if (resid) { v0 += resid[o]; v1 += resid[o + 1]; }
                    }
                    if (Yf) *(float2*)(Yf + o) = make_float2(v0, v1);
                    if (Yh) *(uint32_t*)(Yh + o) = pack2(h16(v0), h16(v1));
                }
            }
        }
    }
}

// ---------------- depthwise 3x3, fp16 input (2 rows x 4 px / thread) ----------------
__global__ void dw3v2h_kernel(const u16* __restrict__ in, const float* __restrict__ w9,
                              float* __restrict__ out, int C, int sh, int total)
{
    int idx = blockIdx.x * 256 + threadIdx.x;
    if (idx >= total) return;
    const int Wn = 1 << sh;
    int xg = (idx & ((Wn >> 2) - 1)) << 2;
    int t = idx >> (sh - 2);
    int ry = t & ((Wn >> 1) - 1);
    int bc = t >> (sh - 1);
    int c = bc % C;
    int y0 = ry << 1;
    const float* wp = w9 + c * 9;
    size_t rowbase = ((size_t)bc << (2 * sh)) + ((size_t)y0 << sh);
    const u16* p = in + rowbase;

    float o0[4] = {0.f, 0.f, 0.f, 0.f};
    float o1[4] = {0.f, 0.f, 0.f, 0.f};
#pragma unroll
    for (int rr = -1; rr <= 2; rr++) {
        int yy = y0 + rr;
        if ((unsigned)yy >= (unsigned)Wn) continue;
        const u16* r = p + ((ptrdiff_t)rr << sh);
        ushort4 v4 = *(const ushort4*)(r + xg);
        float vx = hff(v4.x), vy = hff(v4.y), vz = hff(v4.z), vw = hff(v4.w);
        float left = (xg > 0) ? hff(r[xg - 1]) : 0.f;
        float right = (xg + 4 < Wn) ? hff(r[xg + 4]) : 0.f;
        if (rr <= 1) {
            float w0 = wp[(rr + 1) * 3], w1 = wp[(rr + 1) * 3 + 1], w2 = wp[(rr + 1) * 3 + 2];
            o0[0] += w0 * left + w1 * vx + w2 * vy;
            o0[1] += w0 * vx + w1 * vy + w2 * vz;
            o0[2] += w0 * vy + w1 * vz + w2 * vw;
            o0[3] += w0 * vz + w1 * vw + w2 * right;
        }
        if (rr >= 0) {
            float w0 = wp[rr * 3], w1 = wp[rr * 3 + 1], w2 = wp[rr * 3 + 2];
            o1[0] += w0 * left + w1 * vx + w2 * vy;
            o1[1] += w0 * vx + w1 * vy + w2 * vz;
            o1[2] += w0 * vy + w1 * vz + w2 * vw;
            o1[3] += w0 * vz + w1 * vw + w2 * right;
        }
    }
    *(float4*)(out + rowbase + xg) = make_float4(o0[0], o0[1], o0[2], o0[3]);
    *(float4*)(out + rowbase + Wn + xg) = make_float4(o1[0], o1[1], o1[2], o1[3]);
}

// ---------------- level-0 S = q k^T + fused row sumsq partials ----------------
__global__ void s_accum_kernel(const float* __restrict__ q, const float* __restrict__ kv,
                               float* __restrict__ part, float* __restrict__ pq,
                               float* __restrict__ pk)
{
    int bh = blockIdx.y;
    int b = bh / HEADS, h = bh % HEADS;
    const float* qb = q + ((size_t)b * CC + h * CHD) * HW;
    const float* kb = kv + ((size_t)b * 2 * CC + h * CHD) * HW;
    int n0 = blockIdx.x * 2048;
    __shared__ float qt[32][65], kt[32][65];
    float acc[4] = {0.f, 0.f, 0.f, 0.f};
    float sqq = 0.f, skk = 0.f;
    int tid = threadIdx.x;
    const int rq = tid >> 3, sub = tid & 7;
    for (int ns = 0; ns < 2048; ns += 64) {
#pragma unroll
        for (int r = 0; r < 8; r++) {
            int e = tid + r * 256;
            int c = e >> 6, nn = e & 63;
            qt[c][nn] = qb[(size_t)c * HW + n0 + ns + nn];
            kt[c][nn] = kb[(size_t)c * HW + n0 + ns + nn];
        }
        __syncthreads();
#pragma unroll
        for (int i = 0; i < 4; i++) {
            int pr = i * 256 + tid;
            int c = pr >> 5, d = pr & 31;
            float a = 0.f;
#pragma unroll
            for (int kk = 0; kk < 64; kk++) a += qt[c][kk] * kt[d][kk];
            acc[i] += a;
        }
#pragma unroll
        for (int j = 0; j < 8; j++) {
            float a = qt[rq][sub * 8 + j]; sqq += a * a;
            float b2 = kt[rq][sub * 8 + j]; skk += b2 * b2;
        }
        __syncthreads();
    }
#pragma unroll
    for (int i = 0; i < 4; i++) {
        int pr = i * 256 + tid;
        part[((size_t)blockIdx.x * 24 + bh) * 1024 + pr] = acc[i];
    }
#pragma unroll
    for (int o = 4; o; o >>= 1) {
        sqq += __shfl_down_sync(0xffffffffu, sqq, o, 8);
        skk += __shfl_down_sync(0xffffffffu, skk, o, 8);
    }
    if (sub == 0) {
        pq[(blockIdx.x * 24 + bh) * 32 + rq] = sqq;
        pk[(blockIdx.x * 24 + bh) * 32 + rq] = skk;
    }
}

// ---------------- fused S-reduce + norms + softmax ----------------
__global__ void sred_soft_kernel(const float* __restrict__ part,
                                 const float* __restrict__ pq, const float* __restrict__ pk,
                                 const float* __restrict__ temp0, float* __restrict__ A)
{
    int bh = blockIdx.x;
    int h = bh % HEADS;
    int c = threadIdx.y, d = threadIdx.x;
    int idx = bh * 1024 + c * 32 + d;
    float s = 0.f;
    for (int ck = 0; ck < 32; ck++) s += part[(size_t)ck * 24576 + idx];

    __shared__ float iq[32], ik[32];
    int nrow = bh * 32 + c;
    if (d == 0) {
        float a = 0.f;
        for (int ck = 0; ck < 32; ck++) a += pq[ck * 768 + nrow];
        iq[c] = 1.f / fmaxf(sqrtf(a), 1e-12f);
    }
    if (d == 1) {
        float a = 0.f;
        for (int ck = 0; ck < 32; ck++) a += pk[ck * 768 + nrow];
        ik[c] = 1.f / fmaxf(sqrtf(a), 1e-12f);
    }
    __syncthreads();

    float v = s * iq[c] * ik[d] * temp0[h];
    float m = v;
#pragma unroll
    for (int o = 16; o; o >>= 1) m = fmaxf(m, __shfl_xor_sync(0xffffffffu, m, o));
    float e = fexp(v - m);
    float su = e;
#pragma unroll
    for (int o = 16; o; o >>= 1) su += __shfl_xor_sync(0xffffffffu, su, o);
    A[idx] = e / su;
}

// ---------------- level-0 out = A @ v -> fp16 plane ----------------
__global__ void out0n_kernel(const float* __restrict__ A, const float* __restrict__ kv,
                             u16* __restrict__ oh)
{
    int bh = blockIdx.y;
    int b = bh / HEADS, h = bh % HEADS;
    __shared__ float As[32][33];
    int tid = threadIdx.x;
    for (int e = tid; e < 1024; e += 256) As[e >> 5][e & 31] = A[bh * 1024 + e];
    __syncthreads();
    int n = blockIdx.x * 256 + tid;
    const float* vb = kv + ((size_t)b * 2 * CC + CC + h * CHD) * HW + n;
    float vr[32];
#pragma unroll
    for (int d = 0; d < 32; d++) vr[d] = vb[(size_t)d * HW];
    size_t ob = ((size_t)b * CC + h * CHD) * HW + n;
#pragma unroll
    for (int c = 0; c < 32; c++) {
        float s = 0.f;
#pragma unroll
        for (int d = 0; d < 32; d++) s += As[c][d] * vr[d];
        oh[ob + (size_t)c * HW] = h16(s);
    }
}

// ---------------- avg pool 2x2 (reads fp16 plane) ----------------
__global__ void avgpool_kernel(const u16* __restrict__ xh,
                               float* __restrict__ o, u16* __restrict__ oh)
{
    int idx = blockIdx.x * 256 + threadIdx.x;
    if (idx >= HB * CC * HW2) return;
    int xx = idx & 127;
    int yy = (idx >> 7) & 127;
    int bc = idx >> 14;
    size_t p = (size_t)bc * HW + (yy * 2) * 256 + xx * 2;
    float v = 0.25f * (hff(xh[p]) + hff(xh[p + 1]) + hff(xh[p + 256]) + hff(xh[p + 257]));
    o[idx] = v;
    oh[idx] = h16(v);
}

// ---------------- shifted-window cosine attention ----------------
#define ATS 68
#define WATT_SMEM ((12288 * 4 + 64 * ATS + 384 + 384 + 1352 + 64) * 4)

__global__ void winattn_kernel(const float* __restrict__ qg, const float* __restrict__ kvg,
                               const float* __restrict__ rpbt, const float* __restrict__ temp1,
                               u16* __restrict__ oh)
{
    extern __shared__ float smw[];
    float* qs = smw;
    float* ks = qs + 12288;
    float* vs = ks + 12288;
    float* os = vs + 12288;
    float* at = os + 12288;
    float* inq = at + 64 * ATS;
    float* ink = inq + 384;
    float* rpbs = ink + 384;
    int* lab = (int*)(rpbs + 1352);

    int win = blockIdx.x;
    int img = win >> 8;
    int loc = win & 255;
    int whp = loc >> 4, wwp = loc & 15;
    int kwin = win >> 2;
    int bk = kwin >> 8;
    int loc2 = kwin & 255;
    int gh = loc2 >> 4, gw = loc2 & 15;
    int tid = threadIdx.x;

    for (int e = tid; e < 192 * 64; e += 256) {
        int c = e >> 6, t = e & 63;
        int yy = t >> 3, xx = t & 7;
        int y = (whp * 8 + yy + 4) & 127;
        int x = (wwp * 8 + xx + 4) & 127;
        qs[e] = qg[((size_t)img * CC + c) * HW2 + y * 128 + x];
    }
    for (int e = tid; e < 192 * 64; e += 256) {
        int c = e >> 6, t = e & 63;
        int yy = t >> 3, xx = t & 7;
        int y = (gh * 8 + yy + 4) & 127;
        int x = (gw * 8 + xx + 4) & 127;
        size_t base = ((size_t)bk * 2 * CC + c) * HW2 + y * 128 + x;
        ks[e] = kvg[base];
        vs[e] = kvg[base + (size_t)CC * HW2];
    }
    for (int e = tid; e < 1350; e += 256) {
        int hh = e / 225, ridx = e - hh * 225;
        rpbs[e] = rpbt[ridx * HEADS + hh];
    }
    if (tid < 64) {
        int yy = tid >> 3, xx = tid & 7;
        int py = gh * 8 + yy, px = gw * 8 + xx;
        lab[tid] = (py < 120 ? 0 : (py < 124 ? 1 : 2)) * 3 + (px < 120 ? 0 : (px < 124 ? 1 : 2));
    }
    __syncthreads();

    for (int e = tid; e < 384; e += 256) {
        int h = e >> 6, t = e & 63;
        float sq = 0.f, sk = 0.f;
#pragma unroll
        for (int i = 0; i < 32; i++) {
            float a = qs[(h * 32 + i) * 64 + t]; sq += a * a;
            float b = ks[(h * 32 + i) * 64 + t]; sk += b * b;
        }
        inq[e] = 1.f / fmaxf(sqrtf(sq), 1e-12f);
        ink[e] = 1.f / fmaxf(sqrtf(sk), 1e-12f);
    }
    __syncthreads();

    const int ng = tid >> 4, mg = tid & 15;
    const int n0L = ng * 4, m0L = mg * 4;
    const int i0A = (tid >> 4) * 2;
    const int nVg = tid & 15;

    for (int h = 0; h < HEADS; h++) {
        float tmp = temp1[h];
        {
            float a[4][4];
#pragma unroll
            for (int r = 0; r < 4; r++)
#pragma unroll
                for (int c = 0; c < 4; c++) a[r][c] = 0.f;
            const float* qp = qs + h * 2048 + n0L;
            const float* kp = ks + h * 2048 + m0L;
#pragma unroll
            for (int i = 0; i < 32; i++) {
                float4 qv = *(const float4*)(qp + i * 64);
                float4 kv4 = *(const float4*)(kp + i * 64);
                float qa[4] = {qv.x, qv.y, qv.z, qv.w};
                float ka[4] = {kv4.x, kv4.y, kv4.z, kv4.w};
#pragma unroll
                for (int r = 0; r < 4; r++)
#pragma unroll
                    for (int c = 0; c < 4; c++) a[r][c] = fmaf(qa[r], ka[c], a[r][c]);
            }
#pragma unroll
            for (int r = 0; r < 4; r++) {
                int n = n0L + r;
                int yn = n >> 3, xn = n & 7;
                int ln = lab[n];
                float qn = inq[h * 64 + n] * tmp;
                float4 row;
                float* rp = (float*)&row;
#pragma unroll
                for (int c = 0; c < 4; c++) {
                    int m = m0L + c;
                    int ym = m >> 3, xm = m & 7;
                    float s = a[r][c] * qn * ink[h * 64 + m]
                            + rpbs[h * 225 + (yn - ym + 7) * 15 + (xn - xm + 7)];
                    if (ln != lab[m]) s -= 100.f;
                    rp[c] = s;
                }
                *(float4*)(at + n * ATS + m0L) = row;
            }
        }
        __syncthreads();
        {
            int wid = tid >> 5, lane = tid & 31;
            for (int r = wid; r < 64; r += 8) {
                float v0 = at[r * ATS + lane], v1 = at[r * ATS + lane + 32];
                float mx = fmaxf(v0, v1);
#pragma unroll
                for (int o = 16; o; o >>= 1) mx = fmaxf(mx, __shfl_xor_sync(0xffffffffu, mx, o));
                v0 = fexp(v0 - mx);
                v1 = fexp(v1 - mx);
                float su = v0 + v1;
#pragma unroll
                for (int o = 16; o; o >>= 1) su += __shfl_xor_sync(0xffffffffu, su, o);
                float inv = 1.f / su;
                at[r * ATS + lane] = v0 * inv;
                at[r * ATS + lane + 32] = v1 * inv;
            }
        }
        __syncthreads();
        {
            float o2[2][4];
#pragma unroll
            for (int j = 0; j < 4; j++) { o2[0][j] = 0.f; o2[1][j] = 0.f; }
            const float* vb0 = vs + (h * 32 + i0A) * 64;
            const float* ab = at + nVg * ATS;
#pragma unroll
            for (int m4 = 0; m4 < 16; m4++) {
                float4 v0 = *(const float4*)(vb0 + m4 * 4);
                float4 v1 = *(const float4*)(vb0 + 64 + m4 * 4);
#pragma unroll
                for (int j = 0; j < 4; j++) {
                    float4 aj = *(const float4*)(ab + j * 16 * ATS + m4 * 4);
                    o2[0][j] += v0.x * aj.x + v0.y * aj.y + v0.z * aj.z + v0.w * aj.w;
                    o2[1][j] += v1.x * aj.x + v1.y * aj.y + v1.z * aj.z + v1.w * aj.w;
                }
            }
#pragma unroll
            for (int i = 0; i < 2; i++)
#pragma unroll
                for (int j = 0; j < 4; j++)
                    os[(h * 32 + i0A + i) * 64 + nVg + 16 * j] = o2[i][j];
        }
        __syncthreads();
    }
    for (int e = tid; e < 192 * 64; e += 256) {
        int c = e >> 6, t = e & 63;
        oh[(size_t)c * 262144 + (size_t)win * 64 + t] = h16(os[e]);
    }
}

// ==================================================================
extern "C" void kernel_launch(void* const* d_in, const int* in_sizes, int n_in,
                              void* d_out, int out_size)
{
    const float* x      = (const float*)d_in[0];
    const float* Wq0    = (const float*)d_in[1];
    const float* Wqdw0  = (const float*)d_in[2];
    const float* Wkv0   = (const float*)d_in[3];
    const float* Wkvdw0 = (const float*)d_in[4];
    const float* Wq1    = (const float*)d_in[5];
    const float* Wqdw1  = (const float*)d_in[6];
    const float* Wkv1   = (const float*)d_in[7];
    const float* Wkvdw1 = (const float*)d_in[8];
    const float* Wproj0 = (const float*)d_in[9];
    const float* Wproj1 = (const float*)d_in[10];
    const float* temp0  = (const float*)d_in[11];
    const float* temp1  = (const float*)d_in[12];
    const float* rpbt   = (const float*)d_in[13];
    const float* Wds    = (const float*)d_in[14];
    float* out = (float*)d_out;

    float *A, *B, *A0, *part, *pq, *pk;
    u16 *Xh, *Wh;
    cudaGetSymbolAddress((void**)&A, g_A);
    cudaGetSymbolAddress((void**)&B, g_B);
    cudaGetSymbolAddress((void**)&Xh, g_Xh);
    cudaGetSymbolAddress((void**)&Wh, g_Wh);
    cudaGetSymbolAddress((void**)&A0, g_A0);
    cudaGetSymbolAddress((void**)&part, g_part);
    cudaGetSymbolAddress((void**)&pq, g_pq);
    cudaGetSymbolAddress((void**)&pk, g_pk);

    const size_t OFF50 = 50331648;
    float* A2 = A + OFF50;

    u16* kv0tH = (u16*)A;                 // 201 MB (u16)
    u16* q0tH  = (u16*)A;                 // 100 MB
    u16* P0h   = (u16*)A;
    float* poolF = B;
    u16* poolH = (u16*)(B + 12582912);
    u16* xdsH  = (u16*)(B + 25165824);
    u16* kv1tH = (u16*)(B + 37748736);
    float* kv1 = B + 62914560;
    u16* q1gH  = (u16*)A2;
    u16* W1h   = (u16*)B;

    cudaFuncSetAttribute(mma_gemm2, cudaFuncAttributeMaxDynamicSharedMemorySize, GEMM_SMEM);

    // ---- conversions ----
    cvtw_all_kernel<<<(2048 * CC + 255) / 256, 256>>>(Wq0, Wkv0, Wq1, Wkv1, Wproj0, Wproj1, Wds, Wh);
    cvtx_kernel<<<49152, 256>>>(x, Xh, 12582912);

    // ---------- level 0 ----------
    mma_gemm2<<<dim3(512 * 3, 1, 4), 256, GEMM_SMEM>>>(Xh, Wh + WO_KV0,
                                                       nullptr, nullptr, kv0tH, 2 * CC, HW, 3, 0);
    dw3v2h_kernel<<<(4 * 2 * CC * HW / 8) / 256, 256>>>(kv0tH, Wkvdw0, B, 2 * CC, 8, 4 * 2 * CC * HW / 8);
    mma_gemm2<<<dim3(512 * 2, 1, 4), 256, GEMM_SMEM>>>(Xh, Wh + WO_Q0,
                                                       nullptr, nullptr, q0tH, CC, HW, 2, 0);
    dw3v2h_kernel<<<(4 * CC * HW / 8) / 256, 256>>>(q0tH, Wqdw0, A2, CC, 8, 4 * CC * HW / 8);
    s_accum_kernel<<<dim3(32, 24), 256>>>(A2, B, part, pq, pk);
    sred_soft_kernel<<<24, dim3(32, 32)>>>(part, pq, pk, temp0, A0);
    out0n_kernel<<<dim3(256, 24), 256>>>(A0, B, P0h);
    mma_gemm2<<<dim3(512 * 2, 1, 4), 256, GEMM_SMEM>>>(P0h, Wh + WO_P0,
                                                       nullptr, out, nullptr, CC, HW, 2, 0);

    // ---------- level 1 ----------
    avgpool_kernel<<<(4 * CC * HW2) / 256, 256>>>(Xh, poolF, poolH);
    mma_gemm2<<<dim3(128 * 2, 1, 4), 256, GEMM_SMEM>>>(poolH, Wh + WO_DS,
                                                       poolF, nullptr, xdsH, CC, HW2, 2, 0);
    mma_gemm2<<<dim3(128 * 3, 1, 4), 256, GEMM_SMEM>>>(xdsH, Wh + WO_KV1,
                                                       nullptr, nullptr, kv1tH, 2 * CC, HW2, 3, 0);
    dw3v2h_kernel<<<(4 * 2 * CC * HW2 / 8) / 256, 256>>>(kv1tH, Wkvdw1, kv1, 2 * CC, 7, 4 * 2 * CC * HW2 / 8);
    mma_gemm2<<<dim3(512 * 2, 1, 4), 256, GEMM_SMEM>>>(Xh, Wh + WO_Q1,
                                                       nullptr, nullptr, q1gH, CC, HW, 2, 2);
    dw3v2h_kernel<<<(16 * CC * HW2 / 8) / 256, 256>>>(q1gH, Wqdw1, A, CC, 7, 16 * CC * HW2 / 8);
    {
        cudaFuncSetAttribute(winattn_kernel, cudaFuncAttributeMaxDynamicSharedMemorySize, WATT_SMEM);
        winattn_kernel<<<4096, 256, WATT_SMEM>>>(A, kv1, rpbt, temp1, W1h);
    }
    mma_gemm2<<<dim3(2048 * 2, 1, 1), 256, GEMM_SMEM>>>(W1h, Wh + WO_P1,
                                                        nullptr, out, nullptr, CC, 262144, 2, 3);
}

// round 16
// speedup vs baseline: 1.0088x; 1.0088x over previous
#include <cuda_runtime.h>
#include <cuda_fp16.h>
#include <math.h>
#include <stdint.h>

#define HB 4
#define CC 192
#define HW 65536
#define HW2 16384
#define HEADS 6
#define CHD 32

typedef unsigned short u16;

// ---------------- static scratch ----------------
__device__ float g_A[100663296];      // 402 MB
__device__ float g_B[100663296];      // 402 MB
__device__ u16   g_Xh[50331648];      // x fp16 plane
__device__ u16   g_Wh[393216];        // weights fp16
__device__ float g_part[32 * 24 * 1024];
__device__ float g_A0[24 * 1024];
__device__ float g_pq[24576];
__device__ float g_pk[24576];

#define WO_Q0    0
#define WO_KV0   49152
#define WO_Q1    122880
#define WO_KV1   172032
#define WO_P0    245760
#define WO_P1    294912
#define WO_DS    344064

// ================= helpers =================
__device__ __forceinline__ u16 h16(float v) {
    __half h = __float2half_rn(v);
    return *(u16*)&h;
}
__device__ __forceinline__ float hff(u16 s) {
    __half h = *(__half*)&s;
    return __half2float(h);
}
__device__ __forceinline__ uint32_t pack2(u16 a, u16 b) {
    return (uint32_t)a | ((uint32_t)b << 16);
}
__device__ __forceinline__ uint32_t smem_u32(const void* p) {
    uint32_t a;
    asm("{ .reg .u64 t; cvta.to.shared.u64 t, %1; cvt.u32.u64 %0, t; }" : "=r"(a) : "l"(p));
    return a;
}
__device__ __forceinline__ void mma16816(float* d, const uint32_t* a, const uint32_t* b) {
    asm volatile(
        "mma.sync.aligned.m16n8k16.row.col.f32.f16.f16.f32 "
        "{%0,%1,%2,%3}, {%4,%5,%6,%7}, {%8,%9}, {%0,%1,%2,%3};"
        : "+f"(d[0]), "+f"(d[1]), "+f"(d[2]), "+f"(d[3])
        : "r"(a[0]), "r"(a[1]), "r"(a[2]), "r"(a[3]), "r"(b[0]), "r"(b[1]));
}
__device__ __forceinline__ void ldsm4(uint32_t* r, uint32_t addr) {
    asm volatile("ldmatrix.sync.aligned.m8n8.x4.shared.b16 {%0,%1,%2,%3}, [%4];"
        : "=r"(r[0]), "=r"(r[1]), "=r"(r[2]), "=r"(r[3]) : "r"(addr));
}
__device__ __forceinline__ void ldsm4t(uint32_t* r, uint32_t addr) {
    asm volatile("ldmatrix.sync.aligned.m8n8.x4.trans.shared.b16 {%0,%1,%2,%3}, [%4];"
        : "=r"(r[0]), "=r"(r[1]), "=r"(r[2]), "=r"(r[3]) : "r"(addr));
}
__device__ __forceinline__ void cpa16(uint32_t dst, const void* src) {
    asm volatile("cp.async.cg.shared.global [%0], [%1], 16;" :: "r"(dst), "l"(src));
}
#define CP_COMMIT() asm volatile("cp.async.commit_group;" ::: "memory")
#define CP_WAIT0()  asm volatile("cp.async.wait_group 0;" ::: "memory")
#define CP_WAIT1()  asm volatile("cp.async.wait_group 1;" ::: "memory")

// fast exp on FMA pipe
__device__ __forceinline__ float fexp(float x) {
    float t = x * 1.44269504089f;
    t = fmaxf(t, -126.f);
    float fi = rintf(t);
    float f = t - fi;
    float p = 0.00015403530393f;
    p = fmaf(p, f, 0.00133335581464f);
    p = fmaf(p, f, 0.00961812910763f);
    p = fmaf(p, f, 0.05550410866482f);
    p = fmaf(p, f, 0.24022650695910f);
    p = fmaf(p, f, 0.69314718055995f);
    p = fmaf(p, f, 1.0f);
    int i = (int)fi;
    float s = __int_as_float((i + 127) << 23);
    return p * s;
}

// ---------------- conversion kernels ----------------
__global__ void cvtx_kernel(const float* __restrict__ src, u16* __restrict__ hi, int n4)
{
    int i = blockIdx.x * 256 + threadIdx.x;
    if (i >= n4) return;
    float4 v = *(const float4*)(src + (size_t)i * 4);
    ushort4 hh = {h16(v.x), h16(v.y), h16(v.z), h16(v.w)};
    *(ushort4*)(hi + (size_t)i * 4) = hh;
}

__global__ void cvtw_all_kernel(const float* __restrict__ Wq0, const float* __restrict__ Wkv0,
                                const float* __restrict__ Wq1, const float* __restrict__ Wkv1,
                                const float* __restrict__ Wp0, const float* __restrict__ Wp1,
                                const float* __restrict__ Wds,
                                u16* __restrict__ hi)
{
    int i = blockIdx.x * 256 + threadIdx.x;
    if (i >= 2048 * CC) return;
    int row = i / CC;
    const float* src; int r0, oc;
    if (row < 256)       { src = Wq0;  r0 = 0;    oc = 192; }
    else if (row < 640)  { src = Wkv0; r0 = 256;  oc = 384; }
    else if (row < 896)  { src = Wq1;  r0 = 640;  oc = 192; }
    else if (row < 1280) { src = Wkv1; r0 = 896;  oc = 384; }
    else if (row < 1536) { src = Wp0;  r0 = 1280; oc = 192; }
    else if (row < 1792) { src = Wp1;  r0 = 1536; oc = 192; }
    else                 { src = Wds;  r0 = 1792; oc = 192; }
    int lr = row - r0;
    float v = (lr < oc) ? src[(size_t)lr * CC + (i % CC)] : 0.f;
    hi[i] = h16(v);
}

// ---------------- pipelined fp16 GEMM with row-active tail skip ----------------
#define ASTR 40
#define BSTR 136
#define A_BUF_U (128 * ASTR)
#define B_BUF_U (32 * BSTR)
#define GEMM_SMEM ((2 * A_BUF_U + 2 * B_BUF_U) * 2)

__global__ void __launch_bounds__(256, 2)
mma_gemm2(const u16* __restrict__ Xs, const u16* __restrict__ Wm,
          const float* __restrict__ resid, float* __restrict__ Yf,
          u16* __restrict__ Yh,
          int OC, int P, int ycnt, int mode)
{
    extern __shared__ u16 smu[];
    const uint32_t sbA = smem_u32(smu);
    const uint32_t sbB = sbA + 2 * A_BUF_U * 2;

    const int tid = threadIdx.x;
    const int warp = tid >> 5, lane = tid & 31;
    const int g4 = lane >> 2, t4 = lane & 3;
    const int wm = warp >> 1, wn = warp & 1;
    const int gz = blockIdx.z;
    const int bx = blockIdx.x / ycnt;
    const int by = blockIdx.x - bx * ycnt;
    const int oc0 = by * 128;
    const int p0 = bx * 128;
    const size_t xoff = (size_t)gz * CC * P + p0;

    const bool act0 = (oc0 + wm * 32) < OC;
    const bool act1 = (oc0 + wm * 32 + 16) < OC;

    float acc[2][8][4];
#pragma unroll
    for (int mt = 0; mt < 2; mt++)
#pragma unroll
        for (int nt = 0; nt < 8; nt++)
#pragma unroll
            for (int e = 0; e < 4; e++) acc[mt][nt][e] = 0.f;

    auto prefetch = [&](int kc, int buf) {
        const int kbase = kc * 32;
        const uint32_t abase = sbA + buf * A_BUF_U * 2;
#pragma unroll
        for (int i = 0; i < 2; i++) {
            int op = tid + i * 256;
            int row = op >> 2, cq = op & 3;
            const u16* src = Wm + (size_t)(oc0 + row) * CC + kbase + cq * 8;
            uint32_t dst = abase + (uint32_t)(row * ASTR + cq * 8) * 2;
            cpa16(dst, src);
        }
        const uint32_t bbase = sbB + buf * B_BUF_U * 2;
#pragma unroll
        for (int i = 0; i < 2; i++) {
            int op = tid + i * 256;
            int row = op >> 4, cq = op & 15;
            const u16* src = Xs + xoff + (size_t)(kbase + row) * P + cq * 8;
            uint32_t dst = bbase + (uint32_t)(row * BSTR + cq * 8) * 2;
            cpa16(dst, src);
        }
    };

    prefetch(0, 0);
    CP_COMMIT();

    const int KC = CC / 32;
    for (int kc = 0; kc < KC; kc++) {
        if (kc + 1 < KC) {
            prefetch(kc + 1, (kc + 1) & 1);
            CP_COMMIT();
            CP_WAIT1();
        } else {
            CP_WAIT0();
        }
        __syncthreads();

        if (act0) {
            const int buf = kc & 1;
            const uint32_t aoff = sbA + buf * A_BUF_U * 2;
            const uint32_t boff = sbB + buf * B_BUF_U * 2;
#pragma unroll
            for (int ks = 0; ks < 2; ks++) {
                const int k0 = ks * 16;
                uint32_t ah[2][4];
                {
                    int mrow = wm * 32 + (lane & 15);
                    int kk = k0 + ((lane & 16) >> 1);
                    ldsm4(ah[0], aoff + (uint32_t)(mrow * ASTR + kk) * 2);
                    if (act1)
                        ldsm4(ah[1], aoff + (uint32_t)((mrow + 16) * ASTR + kk) * 2);
                }
#pragma unroll
                for (int np = 0; np < 4; np++) {
                    int krow = k0 + (lane & 15);
                    int ncol = wn * 64 + np * 16 + ((lane & 16) >> 1);
                    uint32_t bh[4];
                    ldsm4t(bh, boff + (uint32_t)(krow * BSTR + ncol) * 2);
#pragma unroll
                    for (int half = 0; half < 2; half++) {
                        int nt = np * 2 + half;
                        uint32_t* bhp = bh + half * 2;
                        mma16816(acc[0][nt], ah[0], bhp);
                        if (act1) mma16816(acc[1][nt], ah[1], bhp);
                    }
                }
            }
        }
        __syncthreads();
    }

#pragma unroll
    for (int mt = 0; mt < 2; mt++) {
        int r0 = oc0 + wm * 32 + mt * 16 + g4;
#pragma unroll
        for (int nt = 0; nt < 8; nt++) {
            int p = p0 + wn * 64 + nt * 8 + t4 * 2;
#pragma unroll
            for (int hrow = 0; hrow < 2; hrow++) {
                int r = r0 + hrow * 8;
                if (r >= OC) continue;
                float v0 = acc[mt][nt][hrow * 2 + 0];
                float v1 = acc[mt][nt][hrow * 2 + 1];
                if (mode == 3) {
                    int w = p >> 6, t = p & 63;
                    int yy = t >> 3, xx = t & 7;
                    int b = w >> 10;
                    int wh = (w >> 5) & 31;
                    int wn2 = w & 31;
                    int y = (wh * 8 + yy + 4) & 255;
                    int x = (wn2 * 8 + xx + 4) & 255;
                    size_t o = ((size_t)b * CC + r) * HW + y * 256 + x;
                    float2 prev = *(float2*)(Yf + o);
                    *(float2*)(Yf + o) = make_float2(prev.x + v0, prev.y + v1);
                } else {
                    size_t o;
                    if (mode == 2) {
                        int sy = p >> 8, sx = p & 255;
                        int wh = sy >> 3, yy = sy & 7;
                        int ww = sx >> 3, xx = sx & 7;
                        int k = wh >> 3;
                        int whp = ((wh & 7) << 1) | (ww >> 4);
                        int wwp = ww & 15;
                        int img = gz * 4 + k;
                        o = ((size_t)img * CC + r) * HW2 + (whp * 8 + yy) * 128 + wwp * 8 + xx;
                    } else {
                        o = ((size_t)gz * OC + r) * P + p;
                        if (resid) { v0 += resid[o]; v1 += resid[o + 1]; }
                    }
                    if (Yf) *(float2*)(Yf + o) = make_float2(v0, v1);
                    if (Yh) *(uint32_t*)(Yh + o) = pack2(h16(v0), h16(v1));
                }
            }
        }
    }
}

// ---------------- depthwise 3x3, fp16 in -> fp16 out (2 rows x 4 px / thread) ----------------
__global__ void dw3hh_kernel(const u16* __restrict__ in, const float* __restrict__ w9,
                             u16* __restrict__ out, int C, int sh, int total)
{
    int idx = blockIdx.x * 256 + threadIdx.x;
    if (idx >= total) return;
    const int Wn = 1 << sh;
    int xg = (idx & ((Wn >> 2) - 1)) << 2;
    int t = idx >> (sh - 2);
    int ry = t & ((Wn >> 1) - 1);
    int bc = t >> (sh - 1);
    int c = bc % C;
    int y0 = ry << 1;
    const float* wp = w9 + c * 9;
    size_t rowbase = ((size_t)bc << (2 * sh)) + ((size_t)y0 << sh);
    const u16* p = in + rowbase;

    float o0[4] = {0.f, 0.f, 0.f, 0.f};
    float o1[4] = {0.f, 0.f, 0.f, 0.f};
#pragma unroll
    for (int rr = -1; rr <= 2; rr++) {
        int yy = y0 + rr;
        if ((unsigned)yy >= (unsigned)Wn) continue;
        const u16* r = p + ((ptrdiff_t)rr << sh);
        ushort4 v4 = *(const ushort4*)(r + xg);
        float vx = hff(v4.x), vy = hff(v4.y), vz = hff(v4.z), vw = hff(v4.w);
        float left = (xg > 0) ? hff(r[xg - 1]) : 0.f;
        float right = (xg + 4 < Wn) ? hff(r[xg + 4]) : 0.f;
        if (rr <= 1) {
            float w0 = wp[(rr + 1) * 3], w1 = wp[(rr + 1) * 3 + 1], w2 = wp[(rr + 1) * 3 + 2];
            o0[0] += w0 * left + w1 * vx + w2 * vy;
            o0[1] += w0 * vx + w1 * vy + w2 * vz;
            o0[2] += w0 * vy + w1 * vz + w2 * vw;
            o0[3] += w0 * vz + w1 * vw + w2 * right;
        }
        if (rr >= 0) {
            float w0 = wp[rr * 3], w1 = wp[rr * 3 + 1], w2 = wp[rr * 3 + 2];
            o1[0] += w0 * left + w1 * vx + w2 * vy;
            o1[1] += w0 * vx + w1 * vy + w2 * vz;
            o1[2] += w0 * vy + w1 * vz + w2 * vw;
            o1[3] += w0 * vz + w1 * vw + w2 * right;
        }
    }
    ushort4 s0 = {h16(o0[0]), h16(o0[1]), h16(o0[2]), h16(o0[3])};
    ushort4 s1 = {h16(o1[0]), h16(o1[1]), h16(o1[2]), h16(o1[3])};
    *(ushort4*)(out + rowbase + xg) = s0;
    *(ushort4*)(out + rowbase + Wn + xg) = s1;
}

// ---------------- level-0 S = q k^T + fused row sumsq partials (fp16 inputs) ----------------
__global__ void s_accum_kernel(const u16* __restrict__ q, const u16* __restrict__ kv,
                               float* __restrict__ part, float* __restrict__ pq,
                               float* __restrict__ pk)
{
    int bh = blockIdx.y;
    int b = bh / HEADS, h = bh % HEADS;
    const u16* qb = q + ((size_t)b * CC + h * CHD) * HW;
    const u16* kb = kv + ((size_t)b * 2 * CC + h * CHD) * HW;
    int n0 = blockIdx.x * 2048;
    __shared__ float qt[32][65], kt[32][65];
    float acc[4] = {0.f, 0.f, 0.f, 0.f};
    float sqq = 0.f, skk = 0.f;
    int tid = threadIdx.x;
    const int rq = tid >> 3, sub = tid & 7;
    for (int ns = 0; ns < 2048; ns += 64) {
#pragma unroll
        for (int r = 0; r < 8; r++) {
            int e = tid + r * 256;
            int c = e >> 6, nn = e & 63;
            qt[c][nn] = hff(qb[(size_t)c * HW + n0 + ns + nn]);
            kt[c][nn] = hff(kb[(size_t)c * HW + n0 + ns + nn]);
        }
        __syncthreads();
#pragma unroll
        for (int i = 0; i < 4; i++) {
            int pr = i * 256 + tid;
            int c = pr >> 5, d = pr & 31;
            float a = 0.f;
#pragma unroll
            for (int kk = 0; kk < 64; kk++) a += qt[c][kk] * kt[d][kk];
            acc[i] += a;
        }
#pragma unroll
        for (int j = 0; j < 8; j++) {
            float a = qt[rq][sub * 8 + j]; sqq += a * a;
            float b2 = kt[rq][sub * 8 + j]; skk += b2 * b2;
        }
        __syncthreads();
    }
#pragma unroll
    for (int i = 0; i < 4; i++) {
        int pr = i * 256 + tid;
        part[((size_t)blockIdx.x * 24 + bh) * 1024 + pr] = acc[i];
    }
#pragma unroll
    for (int o = 4; o; o >>= 1) {
        sqq += __shfl_down_sync(0xffffffffu, sqq, o, 8);
        skk += __shfl_down_sync(0xffffffffu, skk, o, 8);
    }
    if (sub == 0) {
        pq[(blockIdx.x * 24 + bh) * 32 + rq] = sqq;
        pk[(blockIdx.x * 24 + bh) * 32 + rq] = skk;
    }
}

// ---------------- fused S-reduce + norms + softmax ----------------
__global__ void sred_soft_kernel(const float* __restrict__ part,
                                 const float* __restrict__ pq, const float* __restrict__ pk,
                                 const float* __restrict__ temp0, float* __restrict__ A)
{
    int bh = blockIdx.x;
    int h = bh % HEADS;
    int c = threadIdx.y, d = threadIdx.x;
    int idx = bh * 1024 + c * 32 + d;
    float s = 0.f;
    for (int ck = 0; ck < 32; ck++) s += part[(size_t)ck * 24576 + idx];

    __shared__ float iq[32], ik[32];
    int nrow = bh * 32 + c;
    if (d == 0) {
        float a = 0.f;
        for (int ck = 0; ck < 32; ck++) a += pq[ck * 768 + nrow];
        iq[c] = 1.f / fmaxf(sqrtf(a), 1e-12f);
    }
    if (d == 1) {
        float a = 0.f;
        for (int ck = 0; ck < 32; ck++) a += pk[ck * 768 + nrow];
        ik[c] = 1.f / fmaxf(sqrtf(a), 1e-12f);
    }
    __syncthreads();

    float v = s * iq[c] * ik[d] * temp0[h];
    float m = v;
#pragma unroll
    for (int o = 16; o; o >>= 1) m = fmaxf(m, __shfl_xor_sync(0xffffffffu, m, o));
    float e = fexp(v - m);
    float su = e;
#pragma unroll
    for (int o = 16; o; o >>= 1) su += __shfl_xor_sync(0xffffffffu, su, o);
    A[idx] = e / su;
}

// ---------------- level-0 out = A @ v (fp16 v) -> fp16 plane ----------------
__global__ void out0n_kernel(const float* __restrict__ A, const u16* __restrict__ kv,
                             u16* __restrict__ oh)
{
    int bh = blockIdx.y;
    int b = bh / HEADS, h = bh % HEADS;
    __shared__ float As[32][33];
    int tid = threadIdx.x;
    for (int e = tid; e < 1024; e += 256) As[e >> 5][e & 31] = A[bh * 1024 + e];
    __syncthreads();
    int n = blockIdx.x * 256 + tid;
    const u16* vb = kv + ((size_t)b * 2 * CC + CC + h * CHD) * HW + n;
    float vr[32];
#pragma unroll
    for (int d = 0; d < 32; d++) vr[d] = hff(vb[(size_t)d * HW]);
    size_t ob = ((size_t)b * CC + h * CHD) * HW + n;
#pragma unroll
    for (int c = 0; c < 32; c++) {
        float s = 0.f;
#pragma unroll
        for (int d = 0; d < 32; d++) s += As[c][d] * vr[d];
        oh[ob + (size_t)c * HW] = h16(s);
    }
}

// ---------------- avg pool 2x2 (reads fp16 plane) ----------------
__global__ void avgpool_kernel(const u16* __restrict__ xh,
                               float* __restrict__ o, u16* __restrict__ oh)
{
    int idx = blockIdx.x * 256 + threadIdx.x;
    if (idx >= HB * CC * HW2) return;
    int xx = idx & 127;
    int yy = (idx >> 7) & 127;
    int bc = idx >> 14;
    size_t p = (size_t)bc * HW + (yy * 2) * 256 + xx * 2;
    float v = 0.25f * (hff(xh[p]) + hff(xh[p + 1]) + hff(xh[p + 256]) + hff(xh[p + 257]));
    o[idx] = v;
    oh[idx] = h16(v);
}

// ---------------- shifted-window cosine attention (fp16 inputs) ----------------
#define ATS 68
#define WATT_SMEM ((12288 * 4 + 64 * ATS + 384 + 384 + 1352 + 64) * 4)

__global__ void winattn_kernel(const u16* __restrict__ qg, const u16* __restrict__ kvg,
                               const float* __restrict__ rpbt, const float* __restrict__ temp1,
                               u16* __restrict__ oh)
{
    extern __shared__ float smw[];
    float* qs = smw;
    float* ks = qs + 12288;
    float* vs = ks + 12288;
    float* os = vs + 12288;
    float* at = os + 12288;
    float* inq = at + 64 * ATS;
    float* ink = inq + 384;
    float* rpbs = ink + 384;
    int* lab = (int*)(rpbs + 1352);

    int win = blockIdx.x;
    int img = win >> 8;
    int loc = win & 255;
    int whp = loc >> 4, wwp = loc & 15;
    int kwin = win >> 2;
    int bk = kwin >> 8;
    int loc2 = kwin & 255;
    int gh = loc2 >> 4, gw = loc2 & 15;
    int tid = threadIdx.x;

    for (int e = tid; e < 192 * 64; e += 256) {
        int c = e >> 6, t = e & 63;
        int yy = t >> 3, xx = t & 7;
        int y = (whp * 8 + yy + 4) & 127;
        int x = (wwp * 8 + xx + 4) & 127;
        qs[e] = hff(qg[((size_t)img * CC + c) * HW2 + y * 128 + x]);
    }
    for (int e = tid; e < 192 * 64; e += 256) {
        int c = e >> 6, t = e & 63;
        int yy = t >> 3, xx = t & 7;
        int y = (gh * 8 + yy + 4) & 127;
        int x = (gw * 8 + xx + 4) & 127;
        size_t base = ((size_t)bk * 2 * CC + c) * HW2 + y * 128 + x;
        ks[e] = hff(kvg[base]);
        vs[e] = hff(kvg[base + (size_t)CC * HW2]);
    }
    for (int e = tid; e < 1350; e += 256) {
        int hh = e / 225, ridx = e - hh * 225;
        rpbs[e] = rpbt[ridx * HEADS + hh];
    }
    if (tid < 64) {
        int yy = tid >> 3, xx = tid & 7;
        int py = gh * 8 + yy, px = gw * 8 + xx;
        lab[tid] = (py < 120 ? 0 : (py < 124 ? 1 : 2)) * 3 + (px < 120 ? 0 : (px < 124 ? 1 : 2));
    }
    __syncthreads();

    for (int e = tid; e < 384; e += 256) {
        int h = e >> 6, t = e & 63;
        float sq = 0.f, sk = 0.f;
#pragma unroll
        for (int i = 0; i < 32; i++) {
            float a = qs[(h * 32 + i) * 64 + t]; sq += a * a;
            float b = ks[(h * 32 + i) * 64 + t]; sk += b * b;
        }
        inq[e] = 1.f / fmaxf(sqrtf(sq), 1e-12f);
        ink[e] = 1.f / fmaxf(sqrtf(sk), 1e-12f);
    }
    __syncthreads();

    const int ng = tid >> 4, mg = tid & 15;
    const int n0L = ng * 4, m0L = mg * 4;
    const int i0A = (tid >> 4) * 2;
    const int nVg = tid & 15;

    for (int h = 0; h < HEADS; h++) {
        float tmp = temp1[h];
        {
            float a[4][4];
#pragma unroll
            for (int r = 0; r < 4; r++)
#pragma unroll
                for (int c = 0; c < 4; c++) a[r][c] = 0.f;
            const float* qp = qs + h * 2048 + n0L;
            const float* kp = ks + h * 2048 + m0L;
#pragma unroll
            for (int i = 0; i < 32; i++) {
                float4 qv = *(const float4*)(qp + i * 64);
                float4 kv4 = *(const float4*)(kp + i * 64);
                float qa[4] = {qv.x, qv.y, qv.z, qv.w};
                float ka[4] = {kv4.x, kv4.y, kv4.z, kv4.w};
#pragma unroll
                for (int r = 0; r < 4; r++)
#pragma unroll
                    for (int c = 0; c < 4; c++) a[r][c] = fmaf(qa[r], ka[c], a[r][c]);
            }
#pragma unroll
            for (int r = 0; r < 4; r++) {
                int n = n0L + r;
                int yn = n >> 3, xn = n & 7;
                int ln = lab[n];
                float qn = inq[h * 64 + n] * tmp;
                float4 row;
                float* rp = (float*)&row;
#pragma unroll
                for (int c = 0; c < 4; c++) {
                    int m = m0L + c;
                    int ym = m >> 3, xm = m & 7;
                    float s = a[r][c] * qn * ink[h * 64 + m]
                            + rpbs[h * 225 + (yn - ym + 7) * 15 + (xn - xm + 7)];
                    if (ln != lab[m]) s -= 100.f;
                    rp[c] = s;
                }
                *(float4*)(at + n * ATS + m0L) = row;
            }
        }
        __syncthreads();
        {
            int wid = tid >> 5, lane = tid & 31;
            for (int r = wid; r < 64; r += 8) {
                float v0 = at[r * ATS + lane], v1 = at[r * ATS + lane + 32];
                float mx = fmaxf(v0, v1);
#pragma unroll
                for (int o = 16; o; o >>= 1) mx = fmaxf(mx, __shfl_xor_sync(0xffffffffu, mx, o));
                v0 = fexp(v0 - mx);
                v1 = fexp(v1 - mx);
                float su = v0 + v1;
#pragma unroll
                for (int o = 16; o; o >>= 1) su += __shfl_xor_sync(0xffffffffu, su, o);
                float inv = 1.f / su;
                at[r * ATS + lane] = v0 * inv;
                at[r * ATS + lane + 32] = v1 * inv;
            }
        }
        __syncthreads();
        {
            float o2[2][4];
#pragma unroll
            for (int j = 0; j < 4; j++) { o2[0][j] = 0.f; o2[1][j] = 0.f; }
            const float* vb0 = vs + (h * 32 + i0A) * 64;
            const float* ab = at + nVg * ATS;
#pragma unroll
            for (int m4 = 0; m4 < 16; m4++) {
                float4 v0 = *(const float4*)(vb0 + m4 * 4);
                float4 v1 = *(const float4*)(vb0 + 64 + m4 * 4);
#pragma unroll
                for (int j = 0; j < 4; j++) {
                    float4 aj = *(const float4*)(ab + j * 16 * ATS + m4 * 4);
                    o2[0][j] += v0.x * aj.x + v0.y * aj.y + v0.z * aj.z + v0.w * aj.w;
                    o2[1][j] += v1.x * aj.x + v1.y * aj.y + v1.z * aj.z + v1.w * aj.w;
                }
            }
#pragma unroll
            for (int i = 0; i < 2; i++)
#pragma unroll
                for (int j = 0; j < 4; j++)
                    os[(h * 32 + i0A + i) * 64 + nVg + 16 * j] = o2[i][j];
        }
        __syncthreads();
    }
    for (int e = tid; e < 192 * 64; e += 256) {
        int c = e >> 6, t = e & 63;
        oh[(size_t)c * 262144 + (size_t)win * 64 + t] = h16(os[e]);
    }
}

// ==================================================================
extern "C" void kernel_launch(void* const* d_in, const int* in_sizes, int n_in,
                              void* d_out, int out_size)
{
    const float* x      = (const float*)d_in[0];
    const float* Wq0    = (const float*)d_in[1];
    const float* Wqdw0  = (const float*)d_in[2];
    const float* Wkv0   = (const float*)d_in[3];
    const float* Wkvdw0 = (const float*)d_in[4];
    const float* Wq1    = (const float*)d_in[5];
    const float* Wqdw1  = (const float*)d_in[6];
    const float* Wkv1   = (const float*)d_in[7];
    const float* Wkvdw1 = (const float*)d_in[8];
    const float* Wproj0 = (const float*)d_in[9];
    const float* Wproj1 = (const float*)d_in[10];
    const float* temp0  = (const float*)d_in[11];
    const float* temp1  = (const float*)d_in[12];
    const float* rpbt   = (const float*)d_in[13];
    const float* Wds    = (const float*)d_in[14];
    float* out = (float*)d_out;

    float *A, *B, *A0, *part, *pq, *pk;
    u16 *Xh, *Wh;
    cudaGetSymbolAddress((void**)&A, g_A);
    cudaGetSymbolAddress((void**)&B, g_B);
    cudaGetSymbolAddress((void**)&Xh, g_Xh);
    cudaGetSymbolAddress((void**)&Wh, g_Wh);
    cudaGetSymbolAddress((void**)&A0, g_A0);
    cudaGetSymbolAddress((void**)&part, g_part);
    cudaGetSymbolAddress((void**)&pq, g_pq);
    cudaGetSymbolAddress((void**)&pk, g_pk);

    const size_t OFF50 = 50331648;
    float* A2 = A + OFF50;

    // level-0 (u16 buffers)
    u16* kv0tH = (u16*)A;                 // GEMM out (fp16)
    u16* kv0H  = (u16*)B;                 // dw3 out
    u16* q0tH  = (u16*)A;                 // reuse after kv0t consumed
    u16* q0H   = (u16*)A2;                // dw3 out
    u16* P0h   = (u16*)A;                 // out0n out
    // level-1
    float* poolF = B;
    u16* poolH = (u16*)(B + 12582912);
    u16* xdsH  = (u16*)(B + 25165824);
    u16* kv1tH = (u16*)(B + 37748736);
    u16* kv1H  = (u16*)(B + 62914560);
    u16* q1gH  = (u16*)A2;
    u16* q1H   = (u16*)A;
    u16* W1h   = (u16*)B;

    cudaFuncSetAttribute(mma_gemm2, cudaFuncAttributeMaxDynamicSharedMemorySize, GEMM_SMEM);

    // ---- conversions ----
    cvtw_all_kernel<<<(2048 * CC + 255) / 256, 256>>>(Wq0, Wkv0, Wq1, Wkv1, Wproj0, Wproj1, Wds, Wh);
    cvtx_kernel<<<49152, 256>>>(x, Xh, 12582912);

    // ---------- level 0 ----------
    mma_gemm2<<<dim3(512 * 3, 1, 4), 256, GEMM_SMEM>>>(Xh, Wh + WO_KV0,
                                                       nullptr, nullptr, kv0tH, 2 * CC, HW, 3, 0);
    dw3hh_kernel<<<(4 * 2 * CC * HW / 8) / 256, 256>>>(kv0tH, Wkvdw0, kv0H, 2 * CC, 8, 4 * 2 * CC * HW / 8);
    mma_gemm2<<<dim3(512 * 2, 1, 4), 256, GEMM_SMEM>>>(Xh, Wh + WO_Q0,
                                                       nullptr, nullptr, q0tH, CC, HW, 2, 0);
    dw3hh_kernel<<<(4 * CC * HW / 8) / 256, 256>>>(q0tH, Wqdw0, q0H, CC, 8, 4 * CC * HW / 8);
    s_accum_kernel<<<dim3(32, 24), 256>>>(q0H, kv0H, part, pq, pk);
    sred_soft_kernel<<<24, dim3(32, 32)>>>(part, pq, pk, temp0, A0);
    out0n_kernel<<<dim3(256, 24), 256>>>(A0, kv0H, P0h);
    mma_gemm2<<<dim3(512 * 2, 1, 4), 256, GEMM_SMEM>>>(P0h, Wh + WO_P0,
                                                       nullptr, out, nullptr, CC, HW, 2, 0);

    // ---------- level 1 ----------
    avgpool_kernel<<<(4 * CC * HW2) / 256, 256>>>(Xh, poolF, poolH);
    mma_gemm2<<<dim3(128 * 2, 1, 4), 256, GEMM_SMEM>>>(poolH, Wh + WO_DS,
                                                       poolF, nullptr, xdsH, CC, HW2, 2, 0);
    mma_gemm2<<<dim3(128 * 3, 1, 4), 256, GEMM_SMEM>>>(xdsH, Wh + WO_KV1,
                                                       nullptr, nullptr, kv1tH, 2 * CC, HW2, 3, 0);
    dw3hh_kernel<<<(4 * 2 * CC * HW2 / 8) / 256, 256>>>(kv1tH, Wkvdw1, kv1H, 2 * CC, 7, 4 * 2 * CC * HW2 / 8);
    mma_gemm2<<<dim3(512 * 2, 1, 4), 256, GEMM_SMEM>>>(Xh, Wh + WO_Q1,
                                                       nullptr, nullptr, q1gH, CC, HW, 2, 2);
    dw3hh_kernel<<<(16 * CC * HW2 / 8) / 256, 256>>>(q1gH, Wqdw1, q1H, CC, 7, 16 * CC * HW2 / 8);
    {
        cudaFuncSetAttribute(winattn_kernel, cudaFuncAttributeMaxDynamicSharedMemorySize, WATT_SMEM);
        winattn_kernel<<<4096, 256, WATT_SMEM>>>(q1H, kv1H, rpbt, temp1, W1h);
    }
    mma_gemm2<<<dim3(2048 * 2, 1, 1), 256, GEMM_SMEM>>>(W1h, Wh + WO_P1,
                                                        nullptr, out, nullptr, CC, 262144, 2, 3);
}

// round 17
// speedup vs baseline: 1.1253x; 1.1155x over previous
#include <cuda_runtime.h>
#include <cuda_fp16.h>
#include <math.h>
#include <stdint.h>

#define HB 4
#define CC 192
#define HW 65536
#define HW2 16384
#define HEADS 6
#define CHD 32

typedef unsigned short u16;

// ---------------- static scratch ----------------
__device__ float g_A[100663296];      // 402 MB
__device__ float g_B[100663296];      // 402 MB
__device__ u16   g_Xh[50331648];      // x fp16 plane
__device__ u16   g_Wh[393216];        // weights fp16
__device__ float g_part[32 * 24 * 1024];
__device__ float g_A0[24 * 1024];
__device__ float g_pq[24576];
__device__ float g_pk[24576];

#define WO_Q0    0
#define WO_KV0   49152
#define WO_Q1    122880
#define WO_KV1   172032
#define WO_P0    245760
#define WO_P1    294912
#define WO_DS    344064

// ================= helpers =================
__device__ __forceinline__ u16 h16(float v) {
    __half h = __float2half_rn(v);
    return *(u16*)&h;
}
__device__ __forceinline__ float hff(u16 s) {
    __half h = *(__half*)&s;
    return __half2float(h);
}
__device__ __forceinline__ uint32_t pack2(u16 a, u16 b) {
    return (uint32_t)a | ((uint32_t)b << 16);
}
__device__ __forceinline__ uint32_t smem_u32(const void* p) {
    uint32_t a;
    asm("{ .reg .u64 t; cvta.to.shared.u64 t, %1; cvt.u32.u64 %0, t; }" : "=r"(a) : "l"(p));
    return a;
}
__device__ __forceinline__ void mma16816(float* d, const uint32_t* a, const uint32_t* b) {
    asm volatile(
        "mma.sync.aligned.m16n8k16.row.col.f32.f16.f16.f32 "
        "{%0,%1,%2,%3}, {%4,%5,%6,%7}, {%8,%9}, {%0,%1,%2,%3};"
        : "+f"(d[0]), "+f"(d[1]), "+f"(d[2]), "+f"(d[3])
        : "r"(a[0]), "r"(a[1]), "r"(a[2]), "r"(a[3]), "r"(b[0]), "r"(b[1]));
}
__device__ __forceinline__ void ldsm4(uint32_t* r, uint32_t addr) {
    asm volatile("ldmatrix.sync.aligned.m8n8.x4.shared.b16 {%0,%1,%2,%3}, [%4];"
        : "=r"(r[0]), "=r"(r[1]), "=r"(r[2]), "=r"(r[3]) : "r"(addr));
}
__device__ __forceinline__ void ldsm4t(uint32_t* r, uint32_t addr) {
    asm volatile("ldmatrix.sync.aligned.m8n8.x4.trans.shared.b16 {%0,%1,%2,%3}, [%4];"
        : "=r"(r[0]), "=r"(r[1]), "=r"(r[2]), "=r"(r[3]) : "r"(addr));
}
__device__ __forceinline__ void cpa16(uint32_t dst, const void* src) {
    asm volatile("cp.async.cg.shared.global [%0], [%1], 16;" :: "r"(dst), "l"(src));
}
#define CP_COMMIT() asm volatile("cp.async.commit_group;" ::: "memory")
#define CP_WAIT0()  asm volatile("cp.async.wait_group 0;" ::: "memory")
#define CP_WAIT1()  asm volatile("cp.async.wait_group 1;" ::: "memory")

// fast exp on FMA pipe
__device__ __forceinline__ float fexp(float x) {
    float t = x * 1.44269504089f;
    t = fmaxf(t, -126.f);
    float fi = rintf(t);
    float f = t - fi;
    float p = 0.00015403530393f;
    p = fmaf(p, f, 0.00133335581464f);
    p = fmaf(p, f, 0.00961812910763f);
    p = fmaf(p, f, 0.05550410866482f);
    p = fmaf(p, f, 0.24022650695910f);
    p = fmaf(p, f, 0.69314718055995f);
    p = fmaf(p, f, 1.0f);
    int i = (int)fi;
    float s = __int_as_float((i + 127) << 23);
    return p * s;
}

// ---------------- conversion kernels ----------------
__global__ void cvtx_kernel(const float* __restrict__ src, u16* __restrict__ hi, int n4)
{
    int i = blockIdx.x * 256 + threadIdx.x;
    if (i >= n4) return;
    float4 v = *(const float4*)(src + (size_t)i * 4);
    ushort4 hh = {h16(v.x), h16(v.y), h16(v.z), h16(v.w)};
    *(ushort4*)(hi + (size_t)i * 4) = hh;
}

__global__ void cvtw_all_kernel(const float* __restrict__ Wq0, const float* __restrict__ Wkv0,
                                const float* __restrict__ Wq1, const float* __restrict__ Wkv1,
                                const float* __restrict__ Wp0, const float* __restrict__ Wp1,
                                const float* __restrict__ Wds,
                                u16* __restrict__ hi)
{
    int i = blockIdx.x * 256 + threadIdx.x;
    if (i >= 2048 * CC) return;
    int row = i / CC;
    const float* src; int r0, oc;
    if (row < 256)       { src = Wq0;  r0 = 0;    oc = 192; }
    else if (row < 640)  { src = Wkv0; r0 = 256;  oc = 384; }
    else if (row < 896)  { src = Wq1;  r0 = 640;  oc = 192; }
    else if (row < 1280) { src = Wkv1; r0 = 896;  oc = 384; }
    else if (row < 1536) { src = Wp0;  r0 = 1280; oc = 192; }
    else if (row < 1792) { src = Wp1;  r0 = 1536; oc = 192; }
    else                 { src = Wds;  r0 = 1792; oc = 192; }
    int lr = row - r0;
    float v = (lr < oc) ? src[(size_t)lr * CC + (i % CC)] : 0.f;
    hi[i] = h16(v);
}

// ---------------- pipelined fp16 GEMM with row-active tail skip ----------------
#define ASTR 40
#define BSTR 136
#define A_BUF_U (128 * ASTR)
#define B_BUF_U (32 * BSTR)
#define GEMM_SMEM ((2 * A_BUF_U + 2 * B_BUF_U) * 2)

__global__ void __launch_bounds__(256, 2)
mma_gemm2(const u16* __restrict__ Xs, const u16* __restrict__ Wm,
          const float* __restrict__ resid, float* __restrict__ Yf,
          u16* __restrict__ Yh,
          int OC, int P, int ycnt, int mode)
{
    extern __shared__ u16 smu[];
    const uint32_t sbA = smem_u32(smu);
    const uint32_t sbB = sbA + 2 * A_BUF_U * 2;

    const int tid = threadIdx.x;
    const int warp = tid >> 5, lane = tid & 31;
    const int g4 = lane >> 2, t4 = lane & 3;
    const int wm = warp >> 1, wn = warp & 1;
    const int gz = blockIdx.z;
    const int bx = blockIdx.x / ycnt;
    const int by = blockIdx.x - bx * ycnt;
    const int oc0 = by * 128;
    const int p0 = bx * 128;
    const size_t xoff = (size_t)gz * CC * P + p0;

    const bool act0 = (oc0 + wm * 32) < OC;
    const bool act1 = (oc0 + wm * 32 + 16) < OC;

    float acc[2][8][4];
#pragma unroll
    for (int mt = 0; mt < 2; mt++)
#pragma unroll
        for (int nt = 0; nt < 8; nt++)
#pragma unroll
            for (int e = 0; e < 4; e++) acc[mt][nt][e] = 0.f;

    auto prefetch = [&](int kc, int buf) {
        const int kbase = kc * 32;
        const uint32_t abase = sbA + buf * A_BUF_U * 2;
#pragma unroll
        for (int i = 0; i < 2; i++) {
            int op = tid + i * 256;
            int row = op >> 2, cq = op & 3;
            const u16* src = Wm + (size_t)(oc0 + row) * CC + kbase + cq * 8;
            uint32_t dst = abase + (uint32_t)(row * ASTR + cq * 8) * 2;
            cpa16(dst, src);
        }
        const uint32_t bbase = sbB + buf * B_BUF_U * 2;
#pragma unroll
        for (int i = 0; i < 2; i++) {
            int op = tid + i * 256;
            int row = op >> 4, cq = op & 15;
            const u16* src = Xs + xoff + (size_t)(kbase + row) * P + cq * 8;
            uint32_t dst = bbase + (uint32_t)(row * BSTR + cq * 8) * 2;
            cpa16(dst, src);
        }
    };

    prefetch(0, 0);
    CP_COMMIT();

    const int KC = CC / 32;
    for (int kc = 0; kc < KC; kc++) {
        if (kc + 1 < KC) {
            prefetch(kc + 1, (kc + 1) & 1);
            CP_COMMIT();
            CP_WAIT1();
        } else {
            CP_WAIT0();
        }
        __syncthreads();

        if (act0) {
            const int buf = kc & 1;
            const uint32_t aoff = sbA + buf * A_BUF_U * 2;
            const uint32_t boff = sbB + buf * B_BUF_U * 2;
#pragma unroll
            for (int ks = 0; ks < 2; ks++) {
                const int k0 = ks * 16;
                uint32_t ah[2][4];
                {
                    int mrow = wm * 32 + (lane & 15);
                    int kk = k0 + ((lane & 16) >> 1);
                    ldsm4(ah[0], aoff + (uint32_t)(mrow * ASTR + kk) * 2);
                    if (act1)
                        ldsm4(ah[1], aoff + (uint32_t)((mrow + 16) * ASTR + kk) * 2);
                }
#pragma unroll
                for (int np = 0; np < 4; np++) {
                    int krow = k0 + (lane & 15);
                    int ncol = wn * 64 + np * 16 + ((lane & 16) >> 1);
                    uint32_t bh[4];
                    ldsm4t(bh, boff + (uint32_t)(krow * BSTR + ncol) * 2);
#pragma unroll
                    for (int half = 0; half < 2; half++) {
                        int nt = np * 2 + half;
                        uint32_t* bhp = bh + half * 2;
                        mma16816(acc[0][nt], ah[0], bhp);
                        if (act1) mma16816(acc[1][nt], ah[1], bhp);
                    }
                }
            }
        }
        __syncthreads();
    }

#pragma unroll
    for (int mt = 0; mt < 2; mt++) {
        int r0 = oc0 + wm * 32 + mt * 16 + g4;
#pragma unroll
        for (int nt = 0; nt < 8; nt++) {
            int p = p0 + wn * 64 + nt * 8 + t4 * 2;
#pragma unroll
            for (int hrow = 0; hrow < 2; hrow++) {
                int r = r0 + hrow * 8;
                if (r >= OC) continue;
                float v0 = acc[mt][nt][hrow * 2 + 0];
                float v1 = acc[mt][nt][hrow * 2 + 1];
                if (mode == 3) {
                    int w = p >> 6, t = p & 63;
                    int yy = t >> 3, xx = t & 7;
                    int b = w >> 10;
                    int wh = (w >> 5) & 31;
                    int wn2 = w & 31;
                    int y = (wh * 8 + yy + 4) & 255;
                    int x = (wn2 * 8 + xx + 4) & 255;
                    size_t o = ((size_t)b * CC + r) * HW + y * 256 + x;
                    float2 prev = *(float2*)(Yf + o);
                    *(float2*)(Yf + o) = make_float2(prev.x + v0, prev.y + v1);
                } else {
                    size_t o;
                    if (mode == 2) {
                        int sy = p >> 8, sx = p & 255;
                        int wh = sy >> 3, yy = sy & 7;
                        int ww = sx >> 3, xx = sx & 7;
                        int k = wh >> 3;
                        int whp = ((wh & 7) << 1) | (ww >> 4);
                        int wwp = ww & 15;
                        int img = gz * 4 + k;
                        o = ((size_t)img * CC + r) * HW2 + (whp * 8 + yy) * 128 + wwp * 8 + xx;
                    } else {
                        o = ((size_t)gz * OC + r) * P + p;
                        if (resid) { v0 += resid[o]; v1 += resid[o + 1]; }
                    }
                    if (Yf) *(float2*)(Yf + o) = make_float2(v0, v1);
                    if (Yh) *(uint32_t*)(Yh + o) = pack2(h16(v0), h16(v1));
                }
            }
        }
    }
}

// ---------------- depthwise 3x3, fp16 in -> fp16 out ----------------
__global__ void dw3hh_kernel(const u16* __restrict__ in, const float* __restrict__ w9,
                             u16* __restrict__ out, int C, int sh, int total)
{
    int idx = blockIdx.x * 256 + threadIdx.x;
    if (idx >= total) return;
    const int Wn = 1 << sh;
    int xg = (idx & ((Wn >> 2) - 1)) << 2;
    int t = idx >> (sh - 2);
    int ry = t & ((Wn >> 1) - 1);
    int bc = t >> (sh - 1);
    int c = bc % C;
    int y0 = ry << 1;
    const float* wp = w9 + c * 9;
    size_t rowbase = ((size_t)bc << (2 * sh)) + ((size_t)y0 << sh);
    const u16* p = in + rowbase;

    float o0[4] = {0.f, 0.f, 0.f, 0.f};
    float o1[4] = {0.f, 0.f, 0.f, 0.f};
#pragma unroll
    for (int rr = -1; rr <= 2; rr++) {
        int yy = y0 + rr;
        if ((unsigned)yy >= (unsigned)Wn) continue;
        const u16* r = p + ((ptrdiff_t)rr << sh);
        ushort4 v4 = *(const ushort4*)(r + xg);
        float vx = hff(v4.x), vy = hff(v4.y), vz = hff(v4.z), vw = hff(v4.w);
        float left = (xg > 0) ? hff(r[xg - 1]) : 0.f;
        float right = (xg + 4 < Wn) ? hff(r[xg + 4]) : 0.f;
        if (rr <= 1) {
            float w0 = wp[(rr + 1) * 3], w1 = wp[(rr + 1) * 3 + 1], w2 = wp[(rr + 1) * 3 + 2];
            o0[0] += w0 * left + w1 * vx + w2 * vy;
            o0[1] += w0 * vx + w1 * vy + w2 * vz;
            o0[2] += w0 * vy + w1 * vz + w2 * vw;
            o0[3] += w0 * vz + w1 * vw + w2 * right;
        }
        if (rr >= 0) {
            float w0 = wp[rr * 3], w1 = wp[rr * 3 + 1], w2 = wp[rr * 3 + 2];
            o1[0] += w0 * left + w1 * vx + w2 * vy;
            o1[1] += w0 * vx + w1 * vy + w2 * vz;
            o1[2] += w0 * vy + w1 * vz + w2 * vw;
            o1[3] += w0 * vz + w1 * vw + w2 * right;
        }
    }
    ushort4 s0 = {h16(o0[0]), h16(o0[1]), h16(o0[2]), h16(o0[3])};
    ushort4 s1 = {h16(o1[0]), h16(o1[1]), h16(o1[2]), h16(o1[3])};
    *(ushort4*)(out + rowbase + xg) = s0;
    *(ushort4*)(out + rowbase + Wn + xg) = s1;
}

// ---------------- level-0 S = q k^T via mma.sync + fused sumsq ----------------
#define SAK 136
#define SA_TILE (32 * SAK)          // u16 per matrix per stage
#define SA_STAGE (2 * SA_TILE)
#define SACC_SMEM (2 * SA_STAGE * 2)   // 34816 B (also covers 8*1056*4 = 33792 reduce)

__global__ void __launch_bounds__(256, 4)
s_accum_mma(const u16* __restrict__ q, const u16* __restrict__ kv,
            float* __restrict__ part, float* __restrict__ pq, float* __restrict__ pk)
{
    extern __shared__ u16 sac[];
    const uint32_t sb = smem_u32(sac);
    int bh = blockIdx.y;
    int b = bh / HEADS, h = bh % HEADS;
    const u16* qb = q + ((size_t)b * CC + h * CHD) * HW;
    const u16* kb = kv + ((size_t)b * 2 * CC + h * CHD) * HW;
    const int n0 = blockIdx.x * 2048;
    const int tid = threadIdx.x, warp = tid >> 5, lane = tid & 31;

    float acc[2][4][4];
#pragma unroll
    for (int mt = 0; mt < 2; mt++)
#pragma unroll
        for (int n8 = 0; n8 < 4; n8++)
#pragma unroll
            for (int e = 0; e < 4; e++) acc[mt][n8][e] = 0.f;

    auto pf = [&](int st, int buf) {
        const uint32_t base = sb + buf * SA_STAGE * 2;
        const int ns = n0 + st * 128;
#pragma unroll
        for (int i = 0; i < 2; i++) {
            int op = tid + i * 256;
            int row = op >> 4, cq = op & 15;
            cpa16(base + (uint32_t)(row * SAK + cq * 8) * 2,
                  qb + (size_t)row * HW + ns + cq * 8);
        }
#pragma unroll
        for (int i = 0; i < 2; i++) {
            int op = tid + i * 256;
            int row = op >> 4, cq = op & 15;
            cpa16(base + (uint32_t)(SA_TILE + row * SAK + cq * 8) * 2,
                  kb + (size_t)row * HW + ns + cq * 8);
        }
    };

    pf(0, 0);
    CP_COMMIT();

    float sqq = 0.f, skk = 0.f;
    const int rq = tid >> 3, sub = tid & 7;
    const int kcol = warp * 16 + ((lane & 16) >> 1);

    for (int st = 0; st < 16; st++) {
        if (st + 1 < 16) {
            pf(st + 1, (st + 1) & 1);
            CP_COMMIT();
            CP_WAIT1();
        } else {
            CP_WAIT0();
        }
        __syncthreads();

        const uint32_t qoff = sb + (st & 1) * SA_STAGE * 2;
        const uint32_t koff = qoff + SA_TILE * 2;
        const u16* qsm = sac + (st & 1) * SA_STAGE;

        // fused sumsq over this 128-k window (8 threads per row, 16 cols each)
#pragma unroll
        for (int j = 0; j < 16; j++) {
            float a = hff(qsm[rq * SAK + sub * 16 + j]); sqq += a * a;
            float b2 = hff(qsm[SA_TILE + rq * SAK + sub * 16 + j]); skk += b2 * b2;
        }

        uint32_t ah0[4], ah1[4], b0[4], b1[4];
        ldsm4(ah0, qoff + (uint32_t)((lane & 15) * SAK + kcol) * 2);
        ldsm4(ah1, qoff + (uint32_t)(((lane & 15) + 16) * SAK + kcol) * 2);
        ldsm4(b0, koff + (uint32_t)((lane & 15) * SAK + kcol) * 2);
        ldsm4(b1, koff + (uint32_t)(((lane & 15) + 16) * SAK + kcol) * 2);
#pragma unroll
        for (int half = 0; half < 2; half++) {
            uint32_t bb[2];
            bb[0] = b0[half]; bb[1] = b0[half + 2];
            mma16816(acc[0][half], ah0, bb);
            mma16816(acc[1][half], ah1, bb);
            bb[0] = b1[half]; bb[1] = b1[half + 2];
            mma16816(acc[0][2 + half], ah0, bb);
            mma16816(acc[1][2 + half], ah1, bb);
        }
        __syncthreads();
    }

    // cross-warp reduction of 32x32 partials
    float* red = (float*)sac;          // 8 * 1056 floats (row stride 33)
    const int rr = lane >> 2, cc2 = (lane & 3) * 2;
#pragma unroll
    for (int mt = 0; mt < 2; mt++)
#pragma unroll
        for (int n8 = 0; n8 < 4; n8++) {
            int base = warp * 1056 + (mt * 16 + rr) * 33 + n8 * 8 + cc2;
            red[base]           = acc[mt][n8][0];
            red[base + 1]       = acc[mt][n8][1];
            red[base + 8 * 33]  = acc[mt][n8][2];
            red[base + 8 * 33 + 1] = acc[mt][n8][3];
        }
    __syncthreads();
#pragma unroll
    for (int i = 0; i < 4; i++) {
        int e = i * 256 + tid;
        int row = e >> 5, col = e & 31;
        float s = 0.f;
#pragma unroll
        for (int w = 0; w < 8; w++) s += red[w * 1056 + row * 33 + col];
        part[((size_t)blockIdx.x * 24 + bh) * 1024 + e] = s;
    }
#pragma unroll
    for (int o = 4; o; o >>= 1) {
        sqq += __shfl_down_sync(0xffffffffu, sqq, o, 8);
        skk += __shfl_down_sync(0xffffffffu, skk, o, 8);
    }
    if (sub == 0) {
        pq[(blockIdx.x * 24 + bh) * 32 + rq] = sqq;
        pk[(blockIdx.x * 24 + bh) * 32 + rq] = skk;
    }
}

// ---------------- fused S-reduce + norms + softmax ----------------
__global__ void sred_soft_kernel(const float* __restrict__ part,
                                 const float* __restrict__ pq, const float* __restrict__ pk,
                                 const float* __restrict__ temp0, float* __restrict__ A)
{
    int bh = blockIdx.x;
    int h = bh % HEADS;
    int c = threadIdx.y, d = threadIdx.x;
    int idx = bh * 1024 + c * 32 + d;
    float s = 0.f;
    for (int ck = 0; ck < 32; ck++) s += part[(size_t)ck * 24576 + idx];

    __shared__ float iq[32], ik[32];
    int nrow = bh * 32 + c;
    if (d == 0) {
        float a = 0.f;
        for (int ck = 0; ck < 32; ck++) a += pq[ck * 768 + nrow];
        iq[c] = 1.f / fmaxf(sqrtf(a), 1e-12f);
    }
    if (d == 1) {
        float a = 0.f;
        for (int ck = 0; ck < 32; ck++) a += pk[ck * 768 + nrow];
        ik[c] = 1.f / fmaxf(sqrtf(a), 1e-12f);
    }
    __syncthreads();

    float v = s * iq[c] * ik[d] * temp0[h];
    float m = v;
#pragma unroll
    for (int o = 16; o; o >>= 1) m = fmaxf(m, __shfl_xor_sync(0xffffffffu, m, o));
    float e = fexp(v - m);
    float su = e;
#pragma unroll
    for (int o = 16; o; o >>= 1) su += __shfl_xor_sync(0xffffffffu, su, o);
    A[idx] = e / su;
}

// ---------------- level-0 out = A @ v (fp16 v) -> fp16 plane ----------------
__global__ void out0n_kernel(const float* __restrict__ A, const u16* __restrict__ kv,
                             u16* __restrict__ oh)
{
    int bh = blockIdx.y;
    int b = bh / HEADS, h = bh % HEADS;
    __shared__ float As[32][33];
    int tid = threadIdx.x;
    for (int e = tid; e < 1024; e += 256) As[e >> 5][e & 31] = A[bh * 1024 + e];
    __syncthreads();
    int n = blockIdx.x * 256 + tid;
    const u16* vb = kv + ((size_t)b * 2 * CC + CC + h * CHD) * HW + n;
    float vr[32];
#pragma unroll
    for (int d = 0; d < 32; d++) vr[d] = hff(vb[(size_t)d * HW]);
    size_t ob = ((size_t)b * CC + h * CHD) * HW + n;
#pragma unroll
    for (int c = 0; c < 32; c++) {
        float s = 0.f;
#pragma unroll
        for (int d = 0; d < 32; d++) s += As[c][d] * vr[d];
        oh[ob + (size_t)c * HW] = h16(s);
    }
}

// ---------------- avg pool 2x2 (reads fp16 plane) ----------------
__global__ void avgpool_kernel(const u16* __restrict__ xh,
                               float* __restrict__ o, u16* __restrict__ oh)
{
    int idx = blockIdx.x * 256 + threadIdx.x;
    if (idx >= HB * CC * HW2) return;
    int xx = idx & 127;
    int yy = (idx >> 7) & 127;
    int bc = idx >> 14;
    size_t p = (size_t)bc * HW + (yy * 2) * 256 + xx * 2;
    float v = 0.25f * (hff(xh[p]) + hff(xh[p + 1]) + hff(xh[p + 256]) + hff(xh[p + 257]));
    o[idx] = v;
    oh[idx] = h16(v);
}

// ---------------- shifted-window cosine attention (fp16 inputs) ----------------
#define ATS 68
#define WATT_SMEM ((12288 * 4 + 64 * ATS + 384 + 384 + 1352 + 64) * 4)

__global__ void winattn_kernel(const u16* __restrict__ qg, const u16* __restrict__ kvg,
                               const float* __restrict__ rpbt, const float* __restrict__ temp1,
                               u16* __restrict__ oh)
{
    extern __shared__ float smw[];
    float* qs = smw;
    float* ks = qs + 12288;
    float* vs = ks + 12288;
    float* os = vs + 12288;
    float* at = os + 12288;
    float* inq = at + 64 * ATS;
    float* ink = inq + 384;
    float* rpbs = ink + 384;
    int* lab = (int*)(rpbs + 1352);

    int win = blockIdx.x;
    int img = win >> 8;
    int loc = win & 255;
    int whp = loc >> 4, wwp = loc & 15;
    int kwin = win >> 2;
    int bk = kwin >> 8;
    int loc2 = kwin & 255;
    int gh = loc2 >> 4, gw = loc2 & 15;
    int tid = threadIdx.x;

    for (int e = tid; e < 192 * 64; e += 256) {
        int c = e >> 6, t = e & 63;
        int yy = t >> 3, xx = t & 7;
        int y = (whp * 8 + yy + 4) & 127;
        int x = (wwp * 8 + xx + 4) & 127;
        qs[e] = hff(qg[((size_t)img * CC + c) * HW2 + y * 128 + x]);
    }
    for (int e = tid; e < 192 * 64; e += 256) {
        int c = e >> 6, t = e & 63;
        int yy = t >> 3, xx = t & 7;
        int y = (gh * 8 + yy + 4) & 127;
        int x = (gw * 8 + xx + 4) & 127;
        size_t base = ((size_t)bk * 2 * CC + c) * HW2 + y * 128 + x;
        ks[e] = hff(kvg[base]);
        vs[e] = hff(kvg[base + (size_t)CC * HW2]);
    }
    for (int e = tid; e < 1350; e += 256) {
        int hh = e / 225, ridx = e - hh * 225;
        rpbs[e] = rpbt[ridx * HEADS + hh];
    }
    if (tid < 64) {
        int yy = tid >> 3, xx = tid & 7;
        int py = gh * 8 + yy, px = gw * 8 + xx;
        lab[tid] = (py < 120 ? 0 : (py < 124 ? 1 : 2)) * 3 + (px < 120 ? 0 : (px < 124 ? 1 : 2));
    }
    __syncthreads();

    for (int e = tid; e < 384; e += 256) {
        int h = e >> 6, t = e & 63;
        float sq = 0.f, sk = 0.f;
#pragma unroll
        for (int i = 0; i < 32; i++) {
            float a = qs[(h * 32 + i) * 64 + t]; sq += a * a;
            float b = ks[(h * 32 + i) * 64 + t]; sk += b * b;
        }
        inq[e] = 1.f / fmaxf(sqrtf(sq), 1e-12f);
        ink[e] = 1.f / fmaxf(sqrtf(sk), 1e-12f);
    }
    __syncthreads();

    const int ng = tid >> 4, mg = tid & 15;
    const int n0L = ng * 4, m0L = mg * 4;
    const int i0A = (tid >> 4) * 2;
    const int nVg = tid & 15;

    for (int h = 0; h < HEADS; h++) {
        float tmp = temp1[h];
        {
            float a[4][4];
#pragma unroll
            for (int r = 0; r < 4; r++)
#pragma unroll
                for (int c = 0; c < 4; c++) a[r][c] = 0.f;
            const float* qp = qs + h * 2048 + n0L;
            const float* kp = ks + h * 2048 + m0L;
#pragma unroll
            for (int i = 0; i < 32; i++) {
                float4 qv = *(const float4*)(qp + i * 64);
                float4 kv4 = *(const float4*)(kp + i * 64);
                float qa[4] = {qv.x, qv.y, qv.z, qv.w};
                float ka[4] = {kv4.x, kv4.y, kv4.z, kv4.w};
#pragma unroll
                for (int r = 0; r < 4; r++)
#pragma unroll
                    for (int c = 0; c < 4; c++) a[r][c] = fmaf(qa[r], ka[c], a[r][c]);
            }
#pragma unroll
            for (int r = 0; r < 4; r++) {
                int n = n0L + r;
                int yn = n >> 3, xn = n & 7;
                int ln = lab[n];
                float qn = inq[h * 64 + n] * tmp;
                float4 row;
                float* rp = (float*)&row;
#pragma unroll
                for (int c = 0; c < 4; c++) {
                    int m = m0L + c;
                    int ym = m >> 3, xm = m & 7;
                    float s = a[r][c] * qn * ink[h * 64 + m]
                            + rpbs[h * 225 + (yn - ym + 7) * 15 + (xn - xm + 7)];
                    if (ln != lab[m]) s -= 100.f;
                    rp[c] = s;
                }
                *(float4*)(at + n * ATS + m0L) = row;
            }
        }
        __syncthreads();
        {
            int wid = tid >> 5, lane = tid & 31;
            for (int r = wid; r < 64; r += 8) {
                float v0 = at[r * ATS + lane], v1 = at[r * ATS + lane + 32];
                float mx = fmaxf(v0, v1);
#pragma unroll
                for (int o = 16; o; o >>= 1) mx = fmaxf(mx, __shfl_xor_sync(0xffffffffu, mx, o));
                v0 = fexp(v0 - mx);
                v1 = fexp(v1 - mx);
                float su = v0 + v1;
#pragma unroll
                for (int o = 16; o; o >>= 1) su += __shfl_xor_sync(0xffffffffu, su, o);
                float inv = 1.f / su;
                at[r * ATS + lane] = v0 * inv;
                at[r * ATS + lane + 32] = v1 * inv;
            }
        }
        __syncthreads();
        {
            float o2[2][4];
#pragma unroll
            for (int j = 0; j < 4; j++) { o2[0][j] = 0.f; o2[1][j] = 0.f; }
            const float* vb0 = vs + (h * 32 + i0A) * 64;
            const float* ab = at + nVg * ATS;
#pragma unroll
            for (int m4 = 0; m4 < 16; m4++) {
                float4 v0 = *(const float4*)(vb0 + m4 * 4);
                float4 v1 = *(const float4*)(vb0 + 64 + m4 * 4);
#pragma unroll
                for (int j = 0; j < 4; j++) {
                    float4 aj = *(const float4*)(ab + j * 16 * ATS + m4 * 4);
                    o2[0][j] += v0.x * aj.x + v0.y * aj.y + v0.z * aj.z + v0.w * aj.w;
                    o2[1][j] += v1.x * aj.x + v1.y * aj.y + v1.z * aj.z + v1.w * aj.w;
                }
            }
#pragma unroll
            for (int i = 0; i < 2; i++)
#pragma unroll
                for (int j = 0; j < 4; j++)
                    os[(h * 32 + i0A + i) * 64 + nVg + 16 * j] = o2[i][j];
        }
        __syncthreads();
    }
    for (int e = tid; e < 192 * 64; e += 256) {
        int c = e >> 6, t = e & 63;
        oh[(size_t)c * 262144 + (size_t)win * 64 + t] = h16(os[e]);
    }
}

// ==================================================================
extern "C" void kernel_launch(void* const* d_in, const int* in_sizes, int n_in,
                              void* d_out, int out_size)
{
    const float* x      = (const float*)d_in[0];
    const float* Wq0    = (const float*)d_in[1];
    const float* Wqdw0  = (const float*)d_in[2];
    const float* Wkv0   = (const float*)d_in[3];
    const float* Wkvdw0 = (const float*)d_in[4];
    const float* Wq1    = (const float*)d_in[5];
    const float* Wqdw1  = (const float*)d_in[6];
    const float* Wkv1   = (const float*)d_in[7];
    const float* Wkvdw1 = (const float*)d_in[8];
    const float* Wproj0 = (const float*)d_in[9];
    const float* Wproj1 = (const float*)d_in[10];
    const float* temp0  = (const float*)d_in[11];
    const float* temp1  = (const float*)d_in[12];
    const float* rpbt   = (const float*)d_in[13];
    const float* Wds    = (const float*)d_in[14];
    float* out = (float*)d_out;

    float *A, *B, *A0, *part, *pq, *pk;
    u16 *Xh, *Wh;
    cudaGetSymbolAddress((void**)&A, g_A);
    cudaGetSymbolAddress((void**)&B, g_B);
    cudaGetSymbolAddress((void**)&Xh, g_Xh);
    cudaGetSymbolAddress((void**)&Wh, g_Wh);
    cudaGetSymbolAddress((void**)&A0, g_A0);
    cudaGetSymbolAddress((void**)&part, g_part);
    cudaGetSymbolAddress((void**)&pq, g_pq);
    cudaGetSymbolAddress((void**)&pk, g_pk);

    const size_t OFF50 = 50331648;
    float* A2 = A + OFF50;

    // level-0 (u16 buffers)
    u16* kv0tH = (u16*)A;
    u16* kv0H  = (u16*)B;
    u16* q0tH  = (u16*)A;
    u16* q0H   = (u16*)A2;
    u16* P0h   = (u16*)A;
    // level-1
    float* poolF = B;
    u16* poolH = (u16*)(B + 12582912);
    u16* xdsH  = (u16*)(B + 25165824);
    u16* kv1tH = (u16*)(B + 37748736);
    u16* kv1H  = (u16*)(B + 62914560);
    u16* q1gH  = (u16*)A2;
    u16* q1H   = (u16*)A;
    u16* W1h   = (u16*)B;

    cudaFuncSetAttribute(mma_gemm2, cudaFuncAttributeMaxDynamicSharedMemorySize, GEMM_SMEM);
    cudaFuncSetAttribute(s_accum_mma, cudaFuncAttributeMaxDynamicSharedMemorySize, SACC_SMEM);

    // ---- conversions ----
    cvtw_all_kernel<<<(2048 * CC + 255) / 256, 256>>>(Wq0, Wkv0, Wq1, Wkv1, Wproj0, Wproj1, Wds, Wh);
    cvtx_kernel<<<49152, 256>>>(x, Xh, 12582912);

    // ---------- level 0 ----------
    mma_gemm2<<<dim3(512 * 3, 1, 4), 256, GEMM_SMEM>>>(Xh, Wh + WO_KV0,
                                                       nullptr, nullptr, kv0tH, 2 * CC, HW, 3, 0);
    dw3hh_kernel<<<(4 * 2 * CC * HW / 8) / 256, 256>>>(kv0tH, Wkvdw0, kv0H, 2 * CC, 8, 4 * 2 * CC * HW / 8);
    mma_gemm2<<<dim3(512 * 2, 1, 4), 256, GEMM_SMEM>>>(Xh, Wh + WO_Q0,
                                                       nullptr, nullptr, q0tH, CC, HW, 2, 0);
    dw3hh_kernel<<<(4 * CC * HW / 8) / 256, 256>>>(q0tH, Wqdw0, q0H, CC, 8, 4 * CC * HW / 8);
    s_accum_mma<<<dim3(32, 24), 256, SACC_SMEM>>>(q0H, kv0H, part, pq, pk);
    sred_soft_kernel<<<24, dim3(32, 32)>>>(part, pq, pk, temp0, A0);
    out0n_kernel<<<dim3(256, 24), 256>>>(A0, kv0H, P0h);
    mma_gemm2<<<dim3(512 * 2, 1, 4), 256, GEMM_SMEM>>>(P0h, Wh + WO_P0,
                                                       nullptr, out, nullptr, CC, HW, 2, 0);

    // ---------- level 1 ----------
    avgpool_kernel<<<(4 * CC * HW2) / 256, 256>>>(Xh, poolF, poolH);
    mma_gemm2<<<dim3(128 * 2, 1, 4), 256, GEMM_SMEM>>>(poolH, Wh + WO_DS,
                                                       poolF, nullptr, xdsH, CC, HW2, 2, 0);
    mma_gemm2<<<dim3(128 * 3, 1, 4), 256, GEMM_SMEM>>>(xdsH, Wh + WO_KV1,
                                                       nullptr, nullptr, kv1tH, 2 * CC, HW2, 3, 0);
    dw3hh_kernel<<<(4 * 2 * CC * HW2 / 8) / 256, 256>>>(kv1tH, Wkvdw1, kv1H, 2 * CC, 7, 4 * 2 * CC * HW2 / 8);
    mma_gemm2<<<dim3(512 * 2, 1, 4), 256, GEMM_SMEM>>>(Xh, Wh + WO_Q1,
                                                       nullptr, nullptr, q1gH, CC, HW, 2, 2);
    dw3hh_kernel<<<(16 * CC * HW2 / 8) / 256, 256>>>(q1gH, Wqdw1, q1H, CC, 7, 16 * CC * HW2 / 8);
    {
        cudaFuncSetAttribute(winattn_kernel, cudaFuncAttributeMaxDynamicSharedMemorySize, WATT_SMEM);
        winattn_kernel<<<4096, 256, WATT_SMEM>>>(q1H, kv1H, rpbt, temp1, W1h);
    }
    mma_gemm2<<<dim3(2048 * 2, 1, 1), 256, GEMM_SMEM>>>(W1h, Wh + WO_P1,
                                                        nullptr, out, nullptr, CC, 262144, 2, 3);
}